// round 7
// baseline (speedup 1.0000x reference)
#include <cuda_runtime.h>
#include <math.h>
#include <stdint.h>

#define BATCH 128
#define SEQL  512
#define CH    321
#define PREDL 336
#define KWIN  25
#define NSEG  128          // SEQL / 4
#define HID   512
#define BC    (BATCH*CH)   // 41088
#define MMLP  (BC*4)       // 164352

// ---------------- static scratch (no allocation allowed) ----------------
__device__ float g_mean[BC];
__device__ float g_std [BC];
__device__ float g_xn  [(size_t)BC*SEQL];      // xn transposed [B*C, L]
// hi/lo tf32-split planes (values are pre-rounded floats; bits == tf32 operand)
__device__ float g_Ah  [(size_t)BC*1024];      // [trend | sea-out], hi plane
__device__ float g_Al  [(size_t)BC*1024];      // lo plane
__device__ float g_xsh [(size_t)MMLP*NSEG];
__device__ float g_xsl [(size_t)MMLP*NSEG];
__device__ float g_hh  [(size_t)MMLP*HID];
__device__ float g_hl  [(size_t)MMLP*HID];
__device__ float g_w11h[NSEG*HID], g_w11l[NSEG*HID];
__device__ float g_w12h[HID*NSEG], g_w12l[HID*NSEG];
__device__ float g_w21h[NSEG*HID], g_w21l[NSEG*HID];
__device__ float g_w22h[HID*NSEG], g_w22l[HID*NSEG];
__device__ float g_w2h [1024*PREDL], g_w2l[1024*PREDL];
__device__ float g_y   [(size_t)BC*PREDL];

__device__ __forceinline__ uint32_t f2tf(float x) {
    uint32_t r;
    asm("cvt.rna.tf32.f32 %0, %1;" : "=r"(r) : "f"(x));
    return r;
}
__device__ __forceinline__ void split2(float v, float& hi, float& lo) {
    uint32_t h = f2tf(v);
    hi = __uint_as_float(h);
    lo = __uint_as_float(f2tf(v - __uint_as_float(h)));
}

// ---------------- stage 1: per-(b,c) mean / std over L ----------------
__global__ void stats_kernel(const float* __restrict__ x) {
    int c = blockIdx.x * 128 + threadIdx.x;
    int b = blockIdx.y;
    if (c >= CH) return;
    const float* p = x + (size_t)b * SEQL * CH + c;
    float s = 0.f, s2 = 0.f;
    #pragma unroll 4
    for (int l = 0; l < SEQL; ++l) {
        float v = p[(size_t)l * CH];
        s  += v;
        s2 += v * v;
    }
    float m   = s  * (1.0f / SEQL);
    float var = s2 * (1.0f / SEQL) - m * m;
    var = fmaxf(var, 0.0f);
    g_mean[b*CH + c] = m;
    g_std [b*CH + c] = sqrtf(var + 1e-5f);
}

// ---------------- stage 2: normalize + transpose to [B*C, L] ----------------
__global__ void norm_transpose_kernel(const float* __restrict__ x,
                                      const float* __restrict__ rw,
                                      const float* __restrict__ rb) {
    __shared__ float sm[32][33];
    int b  = blockIdx.z;
    int l0 = blockIdx.x * 32, c0 = blockIdx.y * 32;
    int tx = threadIdx.x, ty = threadIdx.y;
    int c = c0 + tx, l = l0 + ty;
    if (c < CH) sm[ty][tx] = x[((size_t)b * SEQL + l) * CH + c];
    __syncthreads();
    int cw = c0 + ty, lw = l0 + tx;
    if (cw < CH) {
        float m  = g_mean[b*CH + cw];
        float sd = g_std [b*CH + cw];
        float v  = (sm[tx][ty] - m) / sd * rw[cw] + rb[cw];
        g_xn[((size_t)(b*CH + cw)) * SEQL + lw] = v;
    }
}

// ---------------- stage 3: moving-avg decomp + interleave + split ----------------
__global__ void decomp_kernel() {
    __shared__ float sm[SEQL];
    int row = blockIdx.x;          // b*CH + c
    int l   = threadIdx.x;
    float v = g_xn[(size_t)row * SEQL + l];
    sm[l] = v;
    __syncthreads();
    float s = 0.f;
    #pragma unroll
    for (int d = -12; d <= 12; ++d) {
        int j = l + d;
        j = j < 0 ? 0 : (j > SEQL - 1 ? SEQL - 1 : j);
        s += sm[j];
    }
    float trend = s * (1.0f / KWIN);
    float sea   = v - trend;
    float th, tl, sh, sl;
    split2(trend, th, tl);
    split2(sea,   sh, sl);
    size_t ai = (size_t)row * 1024 + l;                         // head-A cols 0..511
    g_Ah[ai] = th;  g_Al[ai] = tl;
    size_t si = ((size_t)row * 4 + (l & 3)) * NSEG + (l >> 2);  // xs[b,c,s,n]
    g_xsh[si] = sh; g_xsl[si] = sl;
}

// ---------------- weight splitting ----------------
__global__ void split_kernel(const float* __restrict__ src,
                             float* __restrict__ hi, float* __restrict__ lo, int n) {
    int i = blockIdx.x * 256 + threadIdx.x;
    if (i >= n) return;
    float h, l2;
    split2(src[i], h, l2);
    hi[i] = h; lo[i] = l2;
}
__global__ void concat_split_kernel(const float* __restrict__ Wtr,
                                    const float* __restrict__ Wse) {
    int idx = blockIdx.x * 256 + threadIdx.x;
    if (idx >= 1024 * PREDL) return;
    int k = idx / PREDL, p = idx - k * PREDL;
    float v = (k < 512) ? Wtr[(size_t)k * PREDL + p]
                        : Wse[(size_t)(k - 512) * PREDL + p];
    float h, l2;
    split2(v, h, l2);
    g_w2h[idx] = h; g_w2l[idx] = l2;
}

// ======================= tf32x3 tensor-core GEMM, precomputed splits ===========
// C = act(Ahi/lo[M,K] @ Bhi/lo[K,N] + bias [+bias2]); 128x128x16 tiles, 256 thr,
// 8 warps each owning 64x32 of m16n8k8 tf32 frags. Zero cvt in the mainloop.

__device__ __forceinline__ void mma8(float4& d, uint32_t a0, uint32_t a1,
                                     uint32_t a2, uint32_t a3,
                                     uint32_t b0, uint32_t b1) {
    asm volatile(
        "mma.sync.aligned.m16n8k8.row.col.f32.tf32.tf32.f32 "
        "{%0,%1,%2,%3},{%4,%5,%6,%7},{%8,%9},{%0,%1,%2,%3};"
        : "+f"(d.x), "+f"(d.y), "+f"(d.z), "+f"(d.w)
        : "r"(a0), "r"(a1), "r"(a2), "r"(a3), "r"(b0), "r"(b1));
}
__device__ __forceinline__ void cp16(uint32_t dst, const void* src, int bytes) {
    asm volatile("cp.async.cg.shared.global [%0], [%1], 16, %2;\n"
                 :: "r"(dst), "l"(src), "r"(bytes));
}

#define BKT 16
#define APAD 20
#define BPAD 136
#define AS_FLOATS (2*2*128*APAD)                  // 10240
#define SMEM_FLOATS (AS_FLOATS + 2*2*BKT*BPAD)    // 18944
#define SMEM_BYTES  (SMEM_FLOATS*4)               // 75776

// MODE: 0 = plain float out; 1 = split hi/lo out; 2 = split + interleave into A
template<int GELU, int MODE>
__global__ __launch_bounds__(256)
void tgemm_kernel(const float* __restrict__ Ah_, const float* __restrict__ Al_,
                  const float* __restrict__ Bh_, const float* __restrict__ Bl_,
                  const float* __restrict__ bias, const float* __restrict__ bias2,
                  float* __restrict__ Ch, float* __restrict__ Cl,
                  int M, int Kd, int Nd) {
    extern __shared__ float smem[];
    float* Asf = smem;                 // [2][2][128][APAD]
    float* Bsf = smem + AS_FLOATS;     // [2][2][BKT][BPAD]

    const int tid  = threadIdx.x;
    const int lane = tid & 31, wid = tid >> 5;
    const int gid  = lane >> 2, tig = lane & 3;
    const int wm   = (wid & 1) * 64;
    const int wn   = (wid >> 1) * 32;
    const int m0   = blockIdx.y * 128;
    const int n0   = blockIdx.x * 128;

    const uint32_t As_base = (uint32_t)__cvta_generic_to_shared(Asf);
    const uint32_t Bs_base = (uint32_t)__cvta_generic_to_shared(Bsf);

    float4 acc[4][4];
    #pragma unroll
    for (int i = 0; i < 4; ++i)
        #pragma unroll
        for (int j = 0; j < 4; ++j) acc[i][j] = make_float4(0.f, 0.f, 0.f, 0.f);

    auto fill = [&](int t, int buf) {
        const int k0 = t * BKT;
        #pragma unroll
        for (int i = 0; i < 2; ++i) {
            int task = tid + 256 * i;
            // A: 128 rows x 4 chunks of 16B, both planes
            int ar = task >> 2, ac = (task & 3) * 4;
            size_t aoff = (size_t)(m0 + ar) * Kd + k0 + ac;
            uint32_t asm0 = As_base + (uint32_t)((((buf*2+0)*128 + ar)*APAD + ac)*4);
            uint32_t asm1 = As_base + (uint32_t)((((buf*2+1)*128 + ar)*APAD + ac)*4);
            cp16(asm0, Ah_ + aoff, 16);
            cp16(asm1, Al_ + aoff, 16);
            // B: 16 rows x 32 chunks of 16B, both planes (zero-fill past Nd)
            int br = task >> 5, bcc = (task & 31) * 4;
            int bn = n0 + bcc;
            int bytes = (Nd - bn) * 4;
            bytes = bytes < 0 ? 0 : (bytes > 16 ? 16 : bytes);
            size_t boff = (size_t)(k0 + br) * Nd + (bytes > 0 ? bn : 0);
            uint32_t bsm0 = Bs_base + (uint32_t)((((buf*2+0)*BKT + br)*BPAD + bcc)*4);
            uint32_t bsm1 = Bs_base + (uint32_t)((((buf*2+1)*BKT + br)*BPAD + bcc)*4);
            cp16(bsm0, Bh_ + boff, bytes);
            cp16(bsm1, Bl_ + boff, bytes);
        }
    };

    fill(0, 0);
    asm volatile("cp.async.commit_group;");
    asm volatile("cp.async.wait_group 0;");
    __syncthreads();

    const int nk = Kd / BKT;
    for (int t = 0; t < nk; ++t) {
        const int buf = t & 1;
        if (t + 1 < nk) {
            fill(t + 1, buf ^ 1);
            asm volatile("cp.async.commit_group;");
        }
        #pragma unroll
        for (int kk = 0; kk < BKT; kk += 8) {
            uint32_t bh[4][2], bl[4][2];
            #pragma unroll
            for (int nt = 0; nt < 4; ++nt) {
                int col = wn + nt * 8 + gid;
                bh[nt][0] = __float_as_uint(Bsf[(((buf*2+0)*BKT + kk+tig  )*BPAD) + col]);
                bh[nt][1] = __float_as_uint(Bsf[(((buf*2+0)*BKT + kk+tig+4)*BPAD) + col]);
                bl[nt][0] = __float_as_uint(Bsf[(((buf*2+1)*BKT + kk+tig  )*BPAD) + col]);
                bl[nt][1] = __float_as_uint(Bsf[(((buf*2+1)*BKT + kk+tig+4)*BPAD) + col]);
            }
            #pragma unroll
            for (int mt = 0; mt < 4; ++mt) {
                int r0 = wm + mt * 16 + gid;
                uint32_t ah0 = __float_as_uint(Asf[(((buf*2+0)*128 + r0    )*APAD) + kk+tig  ]);
                uint32_t ah1 = __float_as_uint(Asf[(((buf*2+0)*128 + r0 + 8)*APAD) + kk+tig  ]);
                uint32_t ah2 = __float_as_uint(Asf[(((buf*2+0)*128 + r0    )*APAD) + kk+tig+4]);
                uint32_t ah3 = __float_as_uint(Asf[(((buf*2+0)*128 + r0 + 8)*APAD) + kk+tig+4]);
                uint32_t al0 = __float_as_uint(Asf[(((buf*2+1)*128 + r0    )*APAD) + kk+tig  ]);
                uint32_t al1 = __float_as_uint(Asf[(((buf*2+1)*128 + r0 + 8)*APAD) + kk+tig  ]);
                uint32_t al2 = __float_as_uint(Asf[(((buf*2+1)*128 + r0    )*APAD) + kk+tig+4]);
                uint32_t al3 = __float_as_uint(Asf[(((buf*2+1)*128 + r0 + 8)*APAD) + kk+tig+4]);
                #pragma unroll
                for (int nt = 0; nt < 4; ++nt)
                    mma8(acc[mt][nt], ah0, ah1, ah2, ah3, bh[nt][0], bh[nt][1]);
                #pragma unroll
                for (int nt = 0; nt < 4; ++nt)
                    mma8(acc[mt][nt], ah0, ah1, ah2, ah3, bl[nt][0], bl[nt][1]);
                #pragma unroll
                for (int nt = 0; nt < 4; ++nt)
                    mma8(acc[mt][nt], al0, al1, al2, al3, bh[nt][0], bh[nt][1]);
            }
        }
        if (t + 1 < nk) asm volatile("cp.async.wait_group 0;");
        __syncthreads();
    }

    // epilogue
    auto emit = [&](int row, int col, float v) {
        if (col >= Nd) return;
        v += bias[col];
        if (bias2) v += bias2[col];
        if (GELU)  v = 0.5f * v * (1.0f + erff(v * 0.70710678118654752f));
        if (MODE == 0) {
            Ch[(size_t)row * Nd + col] = v;
        } else {
            float h, l2;
            split2(v, h, l2);
            size_t idx = (MODE == 2)
                ? ((size_t)(row >> 2)) * 1024 + 512 + (size_t)col * 4 + (row & 3)
                : (size_t)row * Nd + col;
            Ch[idx] = h;
            Cl[idx] = l2;
        }
    };
    #pragma unroll
    for (int mt = 0; mt < 4; ++mt) {
        int r0 = m0 + wm + mt * 16 + gid;
        #pragma unroll
        for (int nt = 0; nt < 4; ++nt) {
            int c0 = n0 + wn + nt * 8 + 2 * tig;
            float4 c = acc[mt][nt];
            emit(r0,     c0,     c.x);
            emit(r0,     c0 + 1, c.y);
            emit(r0 + 8, c0,     c.z);
            emit(r0 + 8, c0 + 1, c.w);
        }
    }
}

// ---------------- final: denorm + transpose to [B, PRED, C] ----------------
__global__ void final_kernel(const float* __restrict__ rw,
                             const float* __restrict__ rb,
                             float* __restrict__ out) {
    __shared__ float sm[32][33];
    int b  = blockIdx.z;
    int p0 = blockIdx.x * 32, c0 = blockIdx.y * 32;
    int tx = threadIdx.x, ty = threadIdx.y;
    int p = p0 + tx, c = c0 + ty;
    if (p < PREDL && c < CH)
        sm[ty][tx] = g_y[((size_t)(b*CH + c)) * PREDL + p];
    __syncthreads();
    int cw = c0 + tx, pw = p0 + ty;
    if (cw < CH && pw < PREDL) {
        float v = sm[tx][ty];
        v = (v - rb[cw]) / (rw[cw] + 1e-10f);
        v = v * g_std[b*CH + cw] + g_mean[b*CH + cw];
        out[((size_t)b * PREDL + pw) * CH + cw] = v;
    }
}

// ---------------- launch ----------------
extern "C" void kernel_launch(void* const* d_in, const int* in_sizes, int n_in,
                              void* d_out, int out_size) {
    const float* x   = (const float*)d_in[0];
    const float* rw  = (const float*)d_in[1];
    const float* rb  = (const float*)d_in[2];
    const float* W11 = (const float*)d_in[3];
    const float* b11 = (const float*)d_in[4];
    const float* W12 = (const float*)d_in[5];
    const float* b12 = (const float*)d_in[6];
    const float* W21 = (const float*)d_in[7];
    const float* b21 = (const float*)d_in[8];
    const float* W22 = (const float*)d_in[9];
    const float* b22 = (const float*)d_in[10];
    const float* Wtr = (const float*)d_in[11];
    const float* btr = (const float*)d_in[12];
    const float* Wse = (const float*)d_in[13];
    const float* bse = (const float*)d_in[14];
    float* out = (float*)d_out;
    (void)in_sizes; (void)n_in; (void)out_size;

    float *p_Ah, *p_Al, *p_xsh, *p_xsl, *p_hh, *p_hl, *p_y;
    float *p_w11h, *p_w11l, *p_w12h, *p_w12l, *p_w21h, *p_w21l, *p_w22h, *p_w22l;
    float *p_w2h, *p_w2l;
    cudaGetSymbolAddress((void**)&p_Ah,  g_Ah);  cudaGetSymbolAddress((void**)&p_Al,  g_Al);
    cudaGetSymbolAddress((void**)&p_xsh, g_xsh); cudaGetSymbolAddress((void**)&p_xsl, g_xsl);
    cudaGetSymbolAddress((void**)&p_hh,  g_hh);  cudaGetSymbolAddress((void**)&p_hl,  g_hl);
    cudaGetSymbolAddress((void**)&p_w11h, g_w11h); cudaGetSymbolAddress((void**)&p_w11l, g_w11l);
    cudaGetSymbolAddress((void**)&p_w12h, g_w12h); cudaGetSymbolAddress((void**)&p_w12l, g_w12l);
    cudaGetSymbolAddress((void**)&p_w21h, g_w21h); cudaGetSymbolAddress((void**)&p_w21l, g_w21l);
    cudaGetSymbolAddress((void**)&p_w22h, g_w22h); cudaGetSymbolAddress((void**)&p_w22l, g_w22l);
    cudaGetSymbolAddress((void**)&p_w2h, g_w2h);  cudaGetSymbolAddress((void**)&p_w2l, g_w2l);
    cudaGetSymbolAddress((void**)&p_y,   g_y);

    cudaFuncSetAttribute(tgemm_kernel<1,1>, cudaFuncAttributeMaxDynamicSharedMemorySize, SMEM_BYTES);
    cudaFuncSetAttribute(tgemm_kernel<0,1>, cudaFuncAttributeMaxDynamicSharedMemorySize, SMEM_BYTES);
    cudaFuncSetAttribute(tgemm_kernel<0,2>, cudaFuncAttributeMaxDynamicSharedMemorySize, SMEM_BYTES);
    cudaFuncSetAttribute(tgemm_kernel<0,0>, cudaFuncAttributeMaxDynamicSharedMemorySize, SMEM_BYTES);

    // 1) RevIN statistics
    stats_kernel<<<dim3((CH + 127) / 128, BATCH), 128>>>(x);
    // 2) normalize + transpose
    norm_transpose_kernel<<<dim3(SEQL / 32, (CH + 31) / 32, BATCH), dim3(32, 32)>>>(x, rw, rb);
    // 3) decomposition (+ tf32 split of trend/seasonal)
    decomp_kernel<<<BC, SEQL>>>();
    // 3b) split weights
    split_kernel<<<(NSEG*HID + 255) / 256, 256>>>(W11, p_w11h, p_w11l, NSEG*HID);
    split_kernel<<<(HID*NSEG + 255) / 256, 256>>>(W12, p_w12h, p_w12l, HID*NSEG);
    split_kernel<<<(NSEG*HID + 255) / 256, 256>>>(W21, p_w21h, p_w21l, NSEG*HID);
    split_kernel<<<(HID*NSEG + 255) / 256, 256>>>(W22, p_w22h, p_w22l, HID*NSEG);
    concat_split_kernel<<<(1024 * PREDL + 255) / 256, 256>>>(Wtr, Wse);
    // 4) seasonal MLP
    tgemm_kernel<1,1><<<dim3(HID / 128, MMLP / 128), 256, SMEM_BYTES>>>(
        p_xsh, p_xsl, p_w11h, p_w11l, b11, nullptr, p_hh, p_hl, MMLP, NSEG, HID);
    tgemm_kernel<0,1><<<dim3(1,         MMLP / 128), 256, SMEM_BYTES>>>(
        p_hh, p_hl, p_w12h, p_w12l, b12, nullptr, p_xsh, p_xsl, MMLP, HID, NSEG);
    tgemm_kernel<1,1><<<dim3(HID / 128, MMLP / 128), 256, SMEM_BYTES>>>(
        p_xsh, p_xsl, p_w21h, p_w21l, b21, nullptr, p_hh, p_hl, MMLP, NSEG, HID);
    tgemm_kernel<0,2><<<dim3(1,         MMLP / 128), 256, SMEM_BYTES>>>(
        p_hh, p_hl, p_w22h, p_w22l, b22, nullptr, p_Ah, p_Al, MMLP, HID, NSEG);
    // 5) fused heads: [trend|sea] @ [W_tr;W_se]
    tgemm_kernel<0,0><<<dim3((PREDL + 127) / 128, BC / 128), 256, SMEM_BYTES>>>(
        p_Ah, p_Al, p_w2h, p_w2l, btr, bse, p_y, nullptr, BC, 1024, PREDL);
    // 6) denorm + transpose
    final_kernel<<<dim3((PREDL + 31) / 32, (CH + 31) / 32, BATCH), dim3(32, 32)>>>(rw, rb, out);
}

// round 8
// speedup vs baseline: 1.0290x; 1.0290x over previous
#include <cuda_runtime.h>
#include <cuda_bf16.h>
#include <math.h>
#include <stdint.h>

#define BATCH 128
#define SEQL  512
#define CH    321
#define PREDL 336
#define KWIN  25
#define NSEG  128          // SEQL / 4
#define HID   512
#define BC    (BATCH*CH)   // 41088
#define MMLP  (BC*4)       // 164352

typedef __nv_bfloat16 bf16;

// ---------------- static scratch (no allocation allowed) ----------------
__device__ float g_mean[BC];
__device__ float g_std [BC];
__device__ float g_xn  [(size_t)BC*SEQL];        // xn transposed [B*C, L]
// bf16 hi/lo planes of activations (2 bytes each -> same traffic as fp32)
__device__ bf16  g_Abh [(size_t)BC*1024];        // [trend | sea-out] hi
__device__ bf16  g_Abl [(size_t)BC*1024];        // lo
__device__ bf16  g_xsh [(size_t)MMLP*NSEG];
__device__ bf16  g_xsl [(size_t)MMLP*NSEG];
__device__ bf16  g_hh  [(size_t)MMLP*HID];
__device__ bf16  g_hl  [(size_t)MMLP*HID];
// weights pre-packed as k-pair uint32 [(K/2) x N], hi/lo planes
__device__ uint32_t g_w11p[2][(NSEG/2)*HID];
__device__ uint32_t g_w12p[2][(HID/2)*NSEG];
__device__ uint32_t g_w21p[2][(NSEG/2)*HID];
__device__ uint32_t g_w22p[2][(HID/2)*NSEG];
__device__ uint32_t g_w2p [2][512*PREDL];        // concat [W_tr;W_se], K=1024
__device__ float g_y   [(size_t)BC*PREDL];

__device__ __forceinline__ void bsplit(float v, bf16& hi, bf16& lo) {
    hi = __float2bfloat16(v);
    lo = __float2bfloat16(v - __bfloat162float(hi));
}

// ---------------- stage 1: per-(b,c) mean / std over L ----------------
__global__ void stats_kernel(const float* __restrict__ x) {
    int c = blockIdx.x * 128 + threadIdx.x;
    int b = blockIdx.y;
    if (c >= CH) return;
    const float* p = x + (size_t)b * SEQL * CH + c;
    float s = 0.f, s2 = 0.f;
    #pragma unroll 4
    for (int l = 0; l < SEQL; ++l) {
        float v = p[(size_t)l * CH];
        s  += v;
        s2 += v * v;
    }
    float m   = s  * (1.0f / SEQL);
    float var = s2 * (1.0f / SEQL) - m * m;
    var = fmaxf(var, 0.0f);
    g_mean[b*CH + c] = m;
    g_std [b*CH + c] = sqrtf(var + 1e-5f);
}

// ---------------- stage 2: normalize + transpose to [B*C, L] ----------------
__global__ void norm_transpose_kernel(const float* __restrict__ x,
                                      const float* __restrict__ rw,
                                      const float* __restrict__ rb) {
    __shared__ float sm[32][33];
    int b  = blockIdx.z;
    int l0 = blockIdx.x * 32, c0 = blockIdx.y * 32;
    int tx = threadIdx.x, ty = threadIdx.y;
    int c = c0 + tx, l = l0 + ty;
    if (c < CH) sm[ty][tx] = x[((size_t)b * SEQL + l) * CH + c];
    __syncthreads();
    int cw = c0 + ty, lw = l0 + tx;
    if (cw < CH) {
        float m  = g_mean[b*CH + cw];
        float sd = g_std [b*CH + cw];
        float v  = (sm[tx][ty] - m) / sd * rw[cw] + rb[cw];
        g_xn[((size_t)(b*CH + cw)) * SEQL + lw] = v;
    }
}

// ---------------- stage 3: decomp + interleave + bf16 split ----------------
__global__ void decomp_kernel() {
    __shared__ float sm[SEQL];
    int row = blockIdx.x;          // b*CH + c
    int l   = threadIdx.x;
    float v = g_xn[(size_t)row * SEQL + l];
    sm[l] = v;
    __syncthreads();
    float s = 0.f;
    #pragma unroll
    for (int d = -12; d <= 12; ++d) {
        int j = l + d;
        j = j < 0 ? 0 : (j > SEQL - 1 ? SEQL - 1 : j);
        s += sm[j];
    }
    float trend = s * (1.0f / KWIN);
    float sea   = v - trend;
    bf16 th, tl, sh, sl;
    bsplit(trend, th, tl);
    bsplit(sea,   sh, sl);
    size_t ai = (size_t)row * 1024 + l;                         // head-A cols 0..511
    g_Abh[ai] = th;  g_Abl[ai] = tl;
    size_t si = ((size_t)row * 4 + (l & 3)) * NSEG + (l >> 2);  // xs[b,c,s,n]
    g_xsh[si] = sh;  g_xsl[si] = sl;
}

// ---------------- weight packing: [K][N] fp32 -> [K/2][N] uint32 pairs ----------------
__global__ void pack_w_kernel(const float* __restrict__ W,
                              uint32_t* __restrict__ Ph, uint32_t* __restrict__ Pl,
                              int Kd, int Nd) {
    int i = blockIdx.x * 256 + threadIdx.x;
    if (i >= (Kd / 2) * Nd) return;
    int kp = i / Nd, n = i - kp * Nd;
    float v0 = W[(size_t)(2 * kp)     * Nd + n];
    float v1 = W[(size_t)(2 * kp + 1) * Nd + n];
    bf16 h0, l0, h1, l1;
    bsplit(v0, h0, l0);
    bsplit(v1, h1, l1);
    Ph[i] = (uint32_t)__bfloat16_as_ushort(h0) | ((uint32_t)__bfloat16_as_ushort(h1) << 16);
    Pl[i] = (uint32_t)__bfloat16_as_ushort(l0) | ((uint32_t)__bfloat16_as_ushort(l1) << 16);
}
__global__ void pack_w2_kernel(const float* __restrict__ Wtr,
                               const float* __restrict__ Wse,
                               uint32_t* __restrict__ Ph, uint32_t* __restrict__ Pl) {
    int i = blockIdx.x * 256 + threadIdx.x;
    if (i >= 512 * PREDL) return;
    int kp = i / PREDL, n = i - kp * PREDL;
    int k0 = 2 * kp, k1 = 2 * kp + 1;   // both in same half (512-aligned)
    const float* src = (k0 < 512) ? Wtr : Wse;
    int kb = (k0 < 512) ? 0 : 512;
    float v0 = src[(size_t)(k0 - kb) * PREDL + n];
    float v1 = src[(size_t)(k1 - kb) * PREDL + n];
    bf16 h0, l0, h1, l1;
    bsplit(v0, h0, l0);
    bsplit(v1, h1, l1);
    Ph[i] = (uint32_t)__bfloat16_as_ushort(h0) | ((uint32_t)__bfloat16_as_ushort(h1) << 16);
    Pl[i] = (uint32_t)__bfloat16_as_ushort(l0) | ((uint32_t)__bfloat16_as_ushort(l1) << 16);
}

// ======================= bf16x3 tensor-core GEMM =======================
// C = act(A@B + bias [+bias2]) with A,B in (hi,lo) bf16 planes; fp32 accum.
// 128x128x32 tiles, 256 threads, 8 warps each 64x32 of m16n8k16 frags.
// 3 MMA terms: ah*bh + ah*bl + al*bh.

__device__ __forceinline__ void mma16(float4& d, uint32_t a0, uint32_t a1,
                                      uint32_t a2, uint32_t a3,
                                      uint32_t b0, uint32_t b1) {
    asm volatile(
        "mma.sync.aligned.m16n8k16.row.col.f32.bf16.bf16.f32 "
        "{%0,%1,%2,%3},{%4,%5,%6,%7},{%8,%9},{%0,%1,%2,%3};"
        : "+f"(d.x), "+f"(d.y), "+f"(d.z), "+f"(d.w)
        : "r"(a0), "r"(a1), "r"(a2), "r"(a3), "r"(b0), "r"(b1));
}
__device__ __forceinline__ void cp16(uint32_t dst, const void* src, int bytes) {
    asm volatile("cp.async.cg.shared.global [%0], [%1], 16, %2;\n"
                 :: "r"(dst), "l"(src), "r"(bytes));
}

#define BKT 32     // k-depth per tile (elements)
#define PA  20     // A smem row stride in words (16 used)  -> conflict-free
#define PB  136    // B smem row stride in words (128 used) -> conflict-free
#define AS_WORDS (2*2*128*PA)              // 10240
#define BS_WORDS (2*2*16*PB)               // 8704
#define SMEM_BYTES ((AS_WORDS+BS_WORDS)*4) // 75776

// MODE: 0 = fp32 out; 1 = bf16 hi/lo out; 2 = bf16 hi/lo + interleave into A
template<int GELU, int MODE>
__global__ __launch_bounds__(256)
void bgemm_kernel(const bf16* __restrict__ Ah_, const bf16* __restrict__ Al_,
                  const uint32_t* __restrict__ Bhp, const uint32_t* __restrict__ Blp,
                  const float* __restrict__ bias, const float* __restrict__ bias2,
                  float* __restrict__ Cf, bf16* __restrict__ Chb, bf16* __restrict__ Clb,
                  int M, int Kd, int Nd) {
    extern __shared__ uint32_t smw[];
    uint32_t* Asw = smw;              // [2buf][2pl][128][PA]
    uint32_t* Bsw = smw + AS_WORDS;   // [2buf][2pl][16][PB]

    const int tid  = threadIdx.x;
    const int lane = tid & 31, wid = tid >> 5;
    const int gid  = lane >> 2, tig = lane & 3;
    const int wm   = (wid & 1) * 64;
    const int wn   = (wid >> 1) * 32;
    const int m0   = blockIdx.y * 128;
    const int n0   = blockIdx.x * 128;

    const uint32_t As_base = (uint32_t)__cvta_generic_to_shared(Asw);
    const uint32_t Bs_base = (uint32_t)__cvta_generic_to_shared(Bsw);

    float4 acc[4][4];
    #pragma unroll
    for (int i = 0; i < 4; ++i)
        #pragma unroll
        for (int j = 0; j < 4; ++j) acc[i][j] = make_float4(0.f, 0.f, 0.f, 0.f);

    auto fill = [&](int t, int buf) {
        const int k0 = t * BKT;
        // A: 2 planes x 128 rows x 4 chunks(16B=8 bf16) = 1024 chunks
        #pragma unroll
        for (int i = 0; i < 4; ++i) {
            int c = tid + 256 * i;
            int pl = c >> 9, rr = (c >> 2) & 127, ch = c & 3;
            const bf16* src = (pl ? Al_ : Ah_) + (size_t)(m0 + rr) * Kd + k0 + ch * 8;
            uint32_t dst = As_base + (uint32_t)(((((buf*2+pl)*128 + rr) * PA) + ch * 4) * 4);
            cp16(dst, src, 16);
        }
        // B: 2 planes x 16 kpairs x 32 chunks(16B=4 n-words) = 1024 chunks
        #pragma unroll
        for (int i = 0; i < 4; ++i) {
            int c = tid + 256 * i;
            int pl = c >> 9, kp = (c >> 5) & 15, ch = c & 31;
            int bn = n0 + ch * 4;
            int bytes = (Nd - bn) * 4;
            bytes = bytes < 0 ? 0 : (bytes > 16 ? 16 : bytes);
            const uint32_t* src = (pl ? Blp : Bhp) + (size_t)(k0/2 + kp) * Nd + (bytes > 0 ? bn : 0);
            uint32_t dst = Bs_base + (uint32_t)(((((buf*2+pl)*16 + kp) * PB) + ch * 4) * 4);
            cp16(dst, src, bytes);
        }
    };

    fill(0, 0);
    asm volatile("cp.async.commit_group;");
    asm volatile("cp.async.wait_group 0;");
    __syncthreads();

    const int nk = Kd / BKT;
    for (int t = 0; t < nk; ++t) {
        const int buf = t & 1;
        if (t + 1 < nk) {
            fill(t + 1, buf ^ 1);
            asm volatile("cp.async.commit_group;");
        }
        #pragma unroll
        for (int kk2 = 0; kk2 < 16; kk2 += 8) {      // two k16-steps per tile
            uint32_t bh[4][2], bl[4][2];
            #pragma unroll
            for (int nt = 0; nt < 4; ++nt) {
                int col = wn + nt * 8 + gid;
                bh[nt][0] = Bsw[((buf*2+0)*16 + kk2 + tig    ) * PB + col];
                bh[nt][1] = Bsw[((buf*2+0)*16 + kk2 + tig + 4) * PB + col];
                bl[nt][0] = Bsw[((buf*2+1)*16 + kk2 + tig    ) * PB + col];
                bl[nt][1] = Bsw[((buf*2+1)*16 + kk2 + tig + 4) * PB + col];
            }
            #pragma unroll
            for (int mt = 0; mt < 4; ++mt) {
                int r0 = wm + mt * 16 + gid;
                uint32_t ah0 = Asw[((buf*2+0)*128 + r0    ) * PA + kk2 + tig    ];
                uint32_t ah1 = Asw[((buf*2+0)*128 + r0 + 8) * PA + kk2 + tig    ];
                uint32_t ah2 = Asw[((buf*2+0)*128 + r0    ) * PA + kk2 + tig + 4];
                uint32_t ah3 = Asw[((buf*2+0)*128 + r0 + 8) * PA + kk2 + tig + 4];
                uint32_t al0 = Asw[((buf*2+1)*128 + r0    ) * PA + kk2 + tig    ];
                uint32_t al1 = Asw[((buf*2+1)*128 + r0 + 8) * PA + kk2 + tig    ];
                uint32_t al2 = Asw[((buf*2+1)*128 + r0    ) * PA + kk2 + tig + 4];
                uint32_t al3 = Asw[((buf*2+1)*128 + r0 + 8) * PA + kk2 + tig + 4];
                #pragma unroll
                for (int nt = 0; nt < 4; ++nt)
                    mma16(acc[mt][nt], ah0, ah1, ah2, ah3, bh[nt][0], bh[nt][1]);
                #pragma unroll
                for (int nt = 0; nt < 4; ++nt)
                    mma16(acc[mt][nt], ah0, ah1, ah2, ah3, bl[nt][0], bl[nt][1]);
                #pragma unroll
                for (int nt = 0; nt < 4; ++nt)
                    mma16(acc[mt][nt], al0, al1, al2, al3, bh[nt][0], bh[nt][1]);
            }
        }
        if (t + 1 < nk) asm volatile("cp.async.wait_group 0;");
        __syncthreads();
    }

    // epilogue
    auto emit = [&](int row, int col, float v) {
        if (col >= Nd) return;
        v += bias[col];
        if (bias2) v += bias2[col];
        if (GELU)  v = 0.5f * v * (1.0f + erff(v * 0.70710678118654752f));
        if (MODE == 0) {
            Cf[(size_t)row * Nd + col] = v;
        } else {
            bf16 h, l2;
            bsplit(v, h, l2);
            size_t idx = (MODE == 2)
                ? ((size_t)(row >> 2)) * 1024 + 512 + (size_t)col * 4 + (row & 3)
                : (size_t)row * Nd + col;
            Chb[idx] = h;
            Clb[idx] = l2;
        }
    };
    #pragma unroll
    for (int mt = 0; mt < 4; ++mt) {
        int r0 = m0 + wm + mt * 16 + gid;
        #pragma unroll
        for (int nt = 0; nt < 4; ++nt) {
            int c0 = n0 + wn + nt * 8 + 2 * tig;
            float4 c = acc[mt][nt];
            emit(r0,     c0,     c.x);
            emit(r0,     c0 + 1, c.y);
            emit(r0 + 8, c0,     c.z);
            emit(r0 + 8, c0 + 1, c.w);
        }
    }
}

// ---------------- final: denorm + transpose to [B, PRED, C] ----------------
__global__ void final_kernel(const float* __restrict__ rw,
                             const float* __restrict__ rb,
                             float* __restrict__ out) {
    __shared__ float sm[32][33];
    int b  = blockIdx.z;
    int p0 = blockIdx.x * 32, c0 = blockIdx.y * 32;
    int tx = threadIdx.x, ty = threadIdx.y;
    int p = p0 + tx, c = c0 + ty;
    if (p < PREDL && c < CH)
        sm[ty][tx] = g_y[((size_t)(b*CH + c)) * PREDL + p];
    __syncthreads();
    int cw = c0 + tx, pw = p0 + ty;
    if (cw < CH && pw < PREDL) {
        float v = sm[tx][ty];
        v = (v - rb[cw]) / (rw[cw] + 1e-10f);
        v = v * g_std[b*CH + cw] + g_mean[b*CH + cw];
        out[((size_t)b * PREDL + pw) * CH + cw] = v;
    }
}

// ---------------- launch ----------------
extern "C" void kernel_launch(void* const* d_in, const int* in_sizes, int n_in,
                              void* d_out, int out_size) {
    const float* x   = (const float*)d_in[0];
    const float* rw  = (const float*)d_in[1];
    const float* rb  = (const float*)d_in[2];
    const float* W11 = (const float*)d_in[3];
    const float* b11 = (const float*)d_in[4];
    const float* W12 = (const float*)d_in[5];
    const float* b12 = (const float*)d_in[6];
    const float* W21 = (const float*)d_in[7];
    const float* b21 = (const float*)d_in[8];
    const float* W22 = (const float*)d_in[9];
    const float* b22 = (const float*)d_in[10];
    const float* Wtr = (const float*)d_in[11];
    const float* btr = (const float*)d_in[12];
    const float* Wse = (const float*)d_in[13];
    const float* bse = (const float*)d_in[14];
    float* out = (float*)d_out;
    (void)in_sizes; (void)n_in; (void)out_size;

    bf16 *p_Abh, *p_Abl, *p_xsh, *p_xsl, *p_hh, *p_hl;
    uint32_t *p_w11p, *p_w12p, *p_w21p, *p_w22p, *p_w2p;
    float *p_y;
    cudaGetSymbolAddress((void**)&p_Abh, g_Abh); cudaGetSymbolAddress((void**)&p_Abl, g_Abl);
    cudaGetSymbolAddress((void**)&p_xsh, g_xsh); cudaGetSymbolAddress((void**)&p_xsl, g_xsl);
    cudaGetSymbolAddress((void**)&p_hh,  g_hh);  cudaGetSymbolAddress((void**)&p_hl,  g_hl);
    cudaGetSymbolAddress((void**)&p_w11p, g_w11p);
    cudaGetSymbolAddress((void**)&p_w12p, g_w12p);
    cudaGetSymbolAddress((void**)&p_w21p, g_w21p);
    cudaGetSymbolAddress((void**)&p_w22p, g_w22p);
    cudaGetSymbolAddress((void**)&p_w2p,  g_w2p);
    cudaGetSymbolAddress((void**)&p_y,    g_y);

    cudaFuncSetAttribute(bgemm_kernel<1,1>, cudaFuncAttributeMaxDynamicSharedMemorySize, SMEM_BYTES);
    cudaFuncSetAttribute(bgemm_kernel<0,1>, cudaFuncAttributeMaxDynamicSharedMemorySize, SMEM_BYTES);
    cudaFuncSetAttribute(bgemm_kernel<0,2>, cudaFuncAttributeMaxDynamicSharedMemorySize, SMEM_BYTES);
    cudaFuncSetAttribute(bgemm_kernel<0,0>, cudaFuncAttributeMaxDynamicSharedMemorySize, SMEM_BYTES);

    const int W11N = (NSEG/2)*HID, W12N = (HID/2)*NSEG;

    // 1) RevIN statistics
    stats_kernel<<<dim3((CH + 127) / 128, BATCH), 128>>>(x);
    // 2) normalize + transpose
    norm_transpose_kernel<<<dim3(SEQL / 32, (CH + 31) / 32, BATCH), dim3(32, 32)>>>(x, rw, rb);
    // 3) decomposition (+ bf16 split)
    decomp_kernel<<<BC, SEQL>>>();
    // 3b) pack weights into bf16 k-pair planes
    pack_w_kernel<<<(W11N + 255)/256, 256>>>(W11, p_w11p, p_w11p + W11N, NSEG, HID);
    pack_w_kernel<<<(W12N + 255)/256, 256>>>(W12, p_w12p, p_w12p + W12N, HID, NSEG);
    pack_w_kernel<<<(W11N + 255)/256, 256>>>(W21, p_w21p, p_w21p + W11N, NSEG, HID);
    pack_w_kernel<<<(W12N + 255)/256, 256>>>(W22, p_w22p, p_w22p + W12N, HID, NSEG);
    pack_w2_kernel<<<(512 * PREDL + 255)/256, 256>>>(Wtr, Wse, p_w2p, p_w2p + 512*PREDL);
    // 4) seasonal MLP (bf16x3 tensor-core GEMMs)
    bgemm_kernel<1,1><<<dim3(HID / 128, MMLP / 128), 256, SMEM_BYTES>>>(
        p_xsh, p_xsl, p_w11p, p_w11p + W11N, b11, nullptr, nullptr, p_hh, p_hl, MMLP, NSEG, HID);
    bgemm_kernel<0,1><<<dim3(1,         MMLP / 128), 256, SMEM_BYTES>>>(
        p_hh, p_hl, p_w12p, p_w12p + W12N, b12, nullptr, nullptr, p_xsh, p_xsl, MMLP, HID, NSEG);
    bgemm_kernel<1,1><<<dim3(HID / 128, MMLP / 128), 256, SMEM_BYTES>>>(
        p_xsh, p_xsl, p_w21p, p_w21p + W11N, b21, nullptr, nullptr, p_hh, p_hl, MMLP, NSEG, HID);
    bgemm_kernel<0,2><<<dim3(1,         MMLP / 128), 256, SMEM_BYTES>>>(
        p_hh, p_hl, p_w22p, p_w22p + W12N, b22, nullptr, nullptr, p_Abh, p_Abl, MMLP, HID, NSEG);
    // 5) fused heads: [trend|sea] @ [W_tr;W_se] (fp32 out)
    bgemm_kernel<0,0><<<dim3((PREDL + 127) / 128, BC / 128), 256, SMEM_BYTES>>>(
        p_Abh, p_Abl, p_w2p, p_w2p + 512*PREDL, btr, bse, p_y, nullptr, nullptr, BC, 1024, PREDL);
    // 6) denorm + transpose
    final_kernel<<<dim3((PREDL + 31) / 32, (CH + 31) / 32, BATCH), dim3(32, 32)>>>(rw, rb, out);
}

// round 10
// speedup vs baseline: 1.5899x; 1.5450x over previous
#include <cuda_runtime.h>
#include <cuda_bf16.h>
#include <math.h>
#include <stdint.h>

#define BATCH 128
#define SEQL  512
#define CH    321
#define PREDL 336
#define KWIN  25
#define NSEG  128          // SEQL / 4
#define HID   512
#define BC    (BATCH*CH)   // 41088
#define MMLP  (BC*4)       // 164352

typedef __nv_bfloat16 bf16;

// ---------------- static scratch (no allocation allowed) ----------------
__device__ float g_mean[BC];
__device__ float g_std [BC];
__device__ float g_xn  [(size_t)BC*SEQL];        // xn transposed [B*C, L]
// bf16 hi/lo planes of activations (2 bytes each -> same traffic as fp32)
__device__ bf16  g_Abh [(size_t)BC*1024];        // [trend | sea-out] hi
__device__ bf16  g_Abl [(size_t)BC*1024];        // lo
__device__ bf16  g_xsh [(size_t)MMLP*NSEG];
__device__ bf16  g_xsl [(size_t)MMLP*NSEG];
__device__ bf16  g_hh  [(size_t)MMLP*HID];
__device__ bf16  g_hl  [(size_t)MMLP*HID];
// weights pre-packed as k-pair uint32 [(K/2) x N], hi/lo planes
__device__ uint32_t g_w11p[2][(NSEG/2)*HID];
__device__ uint32_t g_w12p[2][(HID/2)*NSEG];
__device__ uint32_t g_w21p[2][(NSEG/2)*HID];
__device__ uint32_t g_w22p[2][(HID/2)*NSEG];
__device__ uint32_t g_w2p [2][512*PREDL];        // concat [W_tr;W_se], K=1024
__device__ float g_y   [(size_t)BC*PREDL];

__device__ __forceinline__ void bsplit(float v, bf16& hi, bf16& lo) {
    hi = __float2bfloat16(v);
    lo = __float2bfloat16(v - __bfloat162float(hi));
}

// ---------------- stage 1: per-(b,c) mean / std over L ----------------
__global__ void stats_kernel(const float* __restrict__ x) {
    int c = blockIdx.x * 128 + threadIdx.x;
    int b = blockIdx.y;
    if (c >= CH) return;
    const float* p = x + (size_t)b * SEQL * CH + c;
    float s = 0.f, s2 = 0.f;
    #pragma unroll 4
    for (int l = 0; l < SEQL; ++l) {
        float v = p[(size_t)l * CH];
        s  += v;
        s2 += v * v;
    }
    float m   = s  * (1.0f / SEQL);
    float var = s2 * (1.0f / SEQL) - m * m;
    var = fmaxf(var, 0.0f);
    g_mean[b*CH + c] = m;
    g_std [b*CH + c] = sqrtf(var + 1e-5f);
}

// ---------------- stage 2: normalize + transpose to [B*C, L] ----------------
__global__ void norm_transpose_kernel(const float* __restrict__ x,
                                      const float* __restrict__ rw,
                                      const float* __restrict__ rb) {
    __shared__ float sm[32][33];
    int b  = blockIdx.z;
    int l0 = blockIdx.x * 32, c0 = blockIdx.y * 32;
    int tx = threadIdx.x, ty = threadIdx.y;
    int c = c0 + tx, l = l0 + ty;
    if (c < CH) sm[ty][tx] = x[((size_t)b * SEQL + l) * CH + c];
    __syncthreads();
    int cw = c0 + ty, lw = l0 + tx;
    if (cw < CH) {
        float m  = g_mean[b*CH + cw];
        float sd = g_std [b*CH + cw];
        float v  = (sm[tx][ty] - m) / sd * rw[cw] + rb[cw];
        g_xn[((size_t)(b*CH + cw)) * SEQL + lw] = v;
    }
}

// ---------------- stage 3: decomp + interleave + bf16 split ----------------
__global__ void decomp_kernel() {
    __shared__ float sm[SEQL];
    int row = blockIdx.x;          // b*CH + c
    int l   = threadIdx.x;
    float v = g_xn[(size_t)row * SEQL + l];
    sm[l] = v;
    __syncthreads();
    float s = 0.f;
    #pragma unroll
    for (int d = -12; d <= 12; ++d) {
        int j = l + d;
        j = j < 0 ? 0 : (j > SEQL - 1 ? SEQL - 1 : j);
        s += sm[j];
    }
    float trend = s * (1.0f / KWIN);
    float sea   = v - trend;
    bf16 th, tl, sh, sl;
    bsplit(trend, th, tl);
    bsplit(sea,   sh, sl);
    size_t ai = (size_t)row * 1024 + l;                         // head-A cols 0..511
    g_Abh[ai] = th;  g_Abl[ai] = tl;
    size_t si = ((size_t)row * 4 + (l & 3)) * NSEG + (l >> 2);  // xs[b,c,s,n]
    g_xsh[si] = sh;  g_xsl[si] = sl;
}

// ---------------- weight packing: [K][N] fp32 -> [K/2][N] uint32 pairs ----------------
__global__ void pack_w_kernel(const float* __restrict__ W,
                              uint32_t* __restrict__ Ph, uint32_t* __restrict__ Pl,
                              int Kd, int Nd) {
    int i = blockIdx.x * 256 + threadIdx.x;
    if (i >= (Kd / 2) * Nd) return;
    int kp = i / Nd, n = i - kp * Nd;
    float v0 = W[(size_t)(2 * kp)     * Nd + n];
    float v1 = W[(size_t)(2 * kp + 1) * Nd + n];
    bf16 h0, l0, h1, l1;
    bsplit(v0, h0, l0);
    bsplit(v1, h1, l1);
    Ph[i] = (uint32_t)__bfloat16_as_ushort(h0) | ((uint32_t)__bfloat16_as_ushort(h1) << 16);
    Pl[i] = (uint32_t)__bfloat16_as_ushort(l0) | ((uint32_t)__bfloat16_as_ushort(l1) << 16);
}
__global__ void pack_w2_kernel(const float* __restrict__ Wtr,
                               const float* __restrict__ Wse,
                               uint32_t* __restrict__ Ph, uint32_t* __restrict__ Pl) {
    int i = blockIdx.x * 256 + threadIdx.x;
    if (i >= 512 * PREDL) return;
    int kp = i / PREDL, n = i - kp * PREDL;
    int k0 = 2 * kp, k1 = 2 * kp + 1;   // both in same half (512-aligned)
    const float* src = (k0 < 512) ? Wtr : Wse;
    int kb = (k0 < 512) ? 0 : 512;
    float v0 = src[(size_t)(k0 - kb) * PREDL + n];
    float v1 = src[(size_t)(k1 - kb) * PREDL + n];
    bf16 h0, l0, h1, l1;
    bsplit(v0, h0, l0);
    bsplit(v1, h1, l1);
    Ph[i] = (uint32_t)__bfloat16_as_ushort(h0) | ((uint32_t)__bfloat16_as_ushort(h1) << 16);
    Pl[i] = (uint32_t)__bfloat16_as_ushort(l0) | ((uint32_t)__bfloat16_as_ushort(l1) << 16);
}

// ======================= bf16x3 tensor-core GEMM =======================
// C = act(A@B + bias [+bias2]) with A,B in (hi,lo) bf16 planes; fp32 accum.
// 128x128x32 tiles, 256 threads, 8 warps each 64x32 of m16n8k16 frags.
// 3 MMA terms per k16: ah*bh + ah*bl + al*bh, issued TERM-MAJOR over an
// mt-pair so accumulator RAW reuse distance is 8 MMAs (was 4).

__device__ __forceinline__ void mma16(float4& d, uint32_t a0, uint32_t a1,
                                      uint32_t a2, uint32_t a3,
                                      uint32_t b0, uint32_t b1) {
    asm volatile(
        "mma.sync.aligned.m16n8k16.row.col.f32.bf16.bf16.f32 "
        "{%0,%1,%2,%3},{%4,%5,%6,%7},{%8,%9},{%0,%1,%2,%3};"
        : "+f"(d.x), "+f"(d.y), "+f"(d.z), "+f"(d.w)
        : "r"(a0), "r"(a1), "r"(a2), "r"(a3), "r"(b0), "r"(b1));
}
__device__ __forceinline__ void cp16(uint32_t dst, const void* src, int bytes) {
    asm volatile("cp.async.cg.shared.global [%0], [%1], 16, %2;\n"
                 :: "r"(dst), "l"(src), "r"(bytes));
}

#define BKT 32     // k-depth per tile (elements)
#define PA  20     // A smem row stride in words (16 used)  -> conflict-free
#define PB  136    // B smem row stride in words (128 used) -> conflict-free
#define AS_WORDS (2*2*128*PA)              // 10240
#define BS_WORDS (2*2*16*PB)               // 8704
#define SMEM_BYTES ((AS_WORDS+BS_WORDS)*4) // 75776

// MODE: 0 = fp32 out; 1 = bf16 hi/lo out; 2 = bf16 hi/lo + interleave into A
template<int GELU, int MODE>
__global__ __launch_bounds__(256)
void bgemm_kernel(const bf16* __restrict__ Ah_, const bf16* __restrict__ Al_,
                  const uint32_t* __restrict__ Bhp, const uint32_t* __restrict__ Blp,
                  const float* __restrict__ bias, const float* __restrict__ bias2,
                  float* __restrict__ Cf, bf16* __restrict__ Chb, bf16* __restrict__ Clb,
                  int M, int Kd, int Nd) {
    extern __shared__ uint32_t smw[];
    uint32_t* Asw = smw;              // [2buf][2pl][128][PA]
    uint32_t* Bsw = smw + AS_WORDS;   // [2buf][2pl][16][PB]

    const int tid  = threadIdx.x;
    const int lane = tid & 31, wid = tid >> 5;
    const int gid  = lane >> 2, tig = lane & 3;
    const int wm   = (wid & 1) * 64;
    const int wn   = (wid >> 1) * 32;
    const int m0   = blockIdx.y * 128;
    const int n0   = blockIdx.x * 128;

    const uint32_t As_base = (uint32_t)__cvta_generic_to_shared(Asw);
    const uint32_t Bs_base = (uint32_t)__cvta_generic_to_shared(Bsw);

    float4 acc[4][4];
    #pragma unroll
    for (int i = 0; i < 4; ++i)
        #pragma unroll
        for (int j = 0; j < 4; ++j) acc[i][j] = make_float4(0.f, 0.f, 0.f, 0.f);

    auto fill = [&](int t, int buf) {
        const int k0 = t * BKT;
        // A: 2 planes x 128 rows x 4 chunks(16B=8 bf16) = 1024 chunks
        #pragma unroll
        for (int i = 0; i < 4; ++i) {
            int c = tid + 256 * i;
            int pl = c >> 9, rr = (c >> 2) & 127, ch = c & 3;
            const bf16* src = (pl ? Al_ : Ah_) + (size_t)(m0 + rr) * Kd + k0 + ch * 8;
            uint32_t dst = As_base + (uint32_t)(((((buf*2+pl)*128 + rr) * PA) + ch * 4) * 4);
            cp16(dst, src, 16);
        }
        // B: 2 planes x 16 kpairs x 32 chunks(16B=4 n-words) = 1024 chunks
        #pragma unroll
        for (int i = 0; i < 4; ++i) {
            int c = tid + 256 * i;
            int pl = c >> 9, kp = (c >> 5) & 15, ch = c & 31;
            int bn = n0 + ch * 4;
            int bytes = (Nd - bn) * 4;
            bytes = bytes < 0 ? 0 : (bytes > 16 ? 16 : bytes);
            const uint32_t* src = (pl ? Blp : Bhp) + (size_t)(k0/2 + kp) * Nd + (bytes > 0 ? bn : 0);
            uint32_t dst = Bs_base + (uint32_t)(((((buf*2+pl)*16 + kp) * PB) + ch * 4) * 4);
            cp16(dst, src, bytes);
        }
    };

    fill(0, 0);
    asm volatile("cp.async.commit_group;");
    asm volatile("cp.async.wait_group 0;");
    __syncthreads();

    const int nk = Kd / BKT;
    for (int t = 0; t < nk; ++t) {
        const int buf = t & 1;
        if (t + 1 < nk) {
            fill(t + 1, buf ^ 1);
            asm volatile("cp.async.commit_group;");
        }
        #pragma unroll
        for (int kk2 = 0; kk2 < 16; kk2 += 8) {      // two k16-steps per tile
            uint32_t bh[4][2], bl[4][2];
            #pragma unroll
            for (int nt = 0; nt < 4; ++nt) {
                int col = wn + nt * 8 + gid;
                bh[nt][0] = Bsw[((buf*2+0)*16 + kk2 + tig    ) * PB + col];
                bh[nt][1] = Bsw[((buf*2+0)*16 + kk2 + tig + 4) * PB + col];
                bl[nt][0] = Bsw[((buf*2+1)*16 + kk2 + tig    ) * PB + col];
                bl[nt][1] = Bsw[((buf*2+1)*16 + kk2 + tig + 4) * PB + col];
            }
            // Process mt in pairs; within a pair issue TERM-MAJOR so each
            // acc register is revisited only every 8 MMAs (hides HMMA latency).
            #pragma unroll
            for (int mp = 0; mp < 2; ++mp) {
                uint32_t ah[2][4], al[2][4];
                #pragma unroll
                for (int m2 = 0; m2 < 2; ++m2) {
                    int r0 = wm + (mp * 2 + m2) * 16 + gid;
                    ah[m2][0] = Asw[((buf*2+0)*128 + r0    ) * PA + kk2 + tig    ];
                    ah[m2][1] = Asw[((buf*2+0)*128 + r0 + 8) * PA + kk2 + tig    ];
                    ah[m2][2] = Asw[((buf*2+0)*128 + r0    ) * PA + kk2 + tig + 4];
                    ah[m2][3] = Asw[((buf*2+0)*128 + r0 + 8) * PA + kk2 + tig + 4];
                    al[m2][0] = Asw[((buf*2+1)*128 + r0    ) * PA + kk2 + tig    ];
                    al[m2][1] = Asw[((buf*2+1)*128 + r0 + 8) * PA + kk2 + tig    ];
                    al[m2][2] = Asw[((buf*2+1)*128 + r0    ) * PA + kk2 + tig + 4];
                    al[m2][3] = Asw[((buf*2+1)*128 + r0 + 8) * PA + kk2 + tig + 4];
                }
                // term 0: ah * bh
                #pragma unroll
                for (int m2 = 0; m2 < 2; ++m2)
                    #pragma unroll
                    for (int nt = 0; nt < 4; ++nt)
                        mma16(acc[mp*2+m2][nt], ah[m2][0], ah[m2][1], ah[m2][2], ah[m2][3],
                              bh[nt][0], bh[nt][1]);
                // term 1: ah * bl
                #pragma unroll
                for (int m2 = 0; m2 < 2; ++m2)
                    #pragma unroll
                    for (int nt = 0; nt < 4; ++nt)
                        mma16(acc[mp*2+m2][nt], ah[m2][0], ah[m2][1], ah[m2][2], ah[m2][3],
                              bl[nt][0], bl[nt][1]);
                // term 2: al * bh
                #pragma unroll
                for (int m2 = 0; m2 < 2; ++m2)
                    #pragma unroll
                    for (int nt = 0; nt < 4; ++nt)
                        mma16(acc[mp*2+m2][nt], al[m2][0], al[m2][1], al[m2][2], al[m2][3],
                              bh[nt][0], bh[nt][1]);
            }
        }
        if (t + 1 < nk) asm volatile("cp.async.wait_group 0;");
        __syncthreads();
    }

    // epilogue
    auto emit = [&](int row, int col, float v) {
        if (col >= Nd) return;
        v += bias[col];
        if (bias2) v += bias2[col];
        if (GELU)  v = 0.5f * v * (1.0f + erff(v * 0.70710678118654752f));
        if (MODE == 0) {
            Cf[(size_t)row * Nd + col] = v;
        } else {
            bf16 h, l2;
            bsplit(v, h, l2);
            size_t idx = (MODE == 2)
                ? ((size_t)(row >> 2)) * 1024 + 512 + (size_t)col * 4 + (row & 3)
                : (size_t)row * Nd + col;
            Chb[idx] = h;
            Clb[idx] = l2;
        }
    };
    #pragma unroll
    for (int mt = 0; mt < 4; ++mt) {
        int r0 = m0 + wm + mt * 16 + gid;
        #pragma unroll
        for (int nt = 0; nt < 4; ++nt) {
            int c0 = n0 + wn + nt * 8 + 2 * tig;
            float4 c = acc[mt][nt];
            emit(r0,     c0,     c.x);
            emit(r0,     c0 + 1, c.y);
            emit(r0 + 8, c0,     c.z);
            emit(r0 + 8, c0 + 1, c.w);
        }
    }
}

// ---------------- final: denorm + transpose to [B, PRED, C] ----------------
__global__ void final_kernel(const float* __restrict__ rw,
                             const float* __restrict__ rb,
                             float* __restrict__ out) {
    __shared__ float sm[32][33];
    int b  = blockIdx.z;
    int p0 = blockIdx.x * 32, c0 = blockIdx.y * 32;
    int tx = threadIdx.x, ty = threadIdx.y;
    int p = p0 + tx, c = c0 + ty;
    if (p < PREDL && c < CH)
        sm[ty][tx] = g_y[((size_t)(b*CH + c)) * PREDL + p];
    __syncthreads();
    int cw = c0 + tx, pw = p0 + ty;
    if (cw < CH && pw < PREDL) {
        float v = sm[tx][ty];
        v = (v - rb[cw]) / (rw[cw] + 1e-10f);
        v = v * g_std[b*CH + cw] + g_mean[b*CH + cw];
        out[((size_t)b * PREDL + pw) * CH + cw] = v;
    }
}

// ---------------- launch ----------------
extern "C" void kernel_launch(void* const* d_in, const int* in_sizes, int n_in,
                              void* d_out, int out_size) {
    const float* x   = (const float*)d_in[0];
    const float* rw  = (const float*)d_in[1];
    const float* rb  = (const float*)d_in[2];
    const float* W11 = (const float*)d_in[3];
    const float* b11 = (const float*)d_in[4];
    const float* W12 = (const float*)d_in[5];
    const float* b12 = (const float*)d_in[6];
    const float* W21 = (const float*)d_in[7];
    const float* b21 = (const float*)d_in[8];
    const float* W22 = (const float*)d_in[9];
    const float* b22 = (const float*)d_in[10];
    const float* Wtr = (const float*)d_in[11];
    const float* btr = (const float*)d_in[12];
    const float* Wse = (const float*)d_in[13];
    const float* bse = (const float*)d_in[14];
    float* out = (float*)d_out;
    (void)in_sizes; (void)n_in; (void)out_size;

    bf16 *p_Abh, *p_Abl, *p_xsh, *p_xsl, *p_hh, *p_hl;
    uint32_t *p_w11p, *p_w12p, *p_w21p, *p_w22p, *p_w2p;
    float *p_y;
    cudaGetSymbolAddress((void**)&p_Abh, g_Abh); cudaGetSymbolAddress((void**)&p_Abl, g_Abl);
    cudaGetSymbolAddress((void**)&p_xsh, g_xsh); cudaGetSymbolAddress((void**)&p_xsl, g_xsl);
    cudaGetSymbolAddress((void**)&p_hh,  g_hh);  cudaGetSymbolAddress((void**)&p_hl,  g_hl);
    cudaGetSymbolAddress((void**)&p_w11p, g_w11p);
    cudaGetSymbolAddress((void**)&p_w12p, g_w12p);
    cudaGetSymbolAddress((void**)&p_w21p, g_w21p);
    cudaGetSymbolAddress((void**)&p_w22p, g_w22p);
    cudaGetSymbolAddress((void**)&p_w2p,  g_w2p);
    cudaGetSymbolAddress((void**)&p_y,    g_y);

    cudaFuncSetAttribute(bgemm_kernel<1,1>, cudaFuncAttributeMaxDynamicSharedMemorySize, SMEM_BYTES);
    cudaFuncSetAttribute(bgemm_kernel<0,1>, cudaFuncAttributeMaxDynamicSharedMemorySize, SMEM_BYTES);
    cudaFuncSetAttribute(bgemm_kernel<0,2>, cudaFuncAttributeMaxDynamicSharedMemorySize, SMEM_BYTES);
    cudaFuncSetAttribute(bgemm_kernel<0,0>, cudaFuncAttributeMaxDynamicSharedMemorySize, SMEM_BYTES);

    const int W11N = (NSEG/2)*HID, W12N = (HID/2)*NSEG;

    // 1) RevIN statistics
    stats_kernel<<<dim3((CH + 127) / 128, BATCH), 128>>>(x);
    // 2) normalize + transpose
    norm_transpose_kernel<<<dim3(SEQL / 32, (CH + 31) / 32, BATCH), dim3(32, 32)>>>(x, rw, rb);
    // 3) decomposition (+ bf16 split)
    decomp_kernel<<<BC, SEQL>>>();
    // 3b) pack weights into bf16 k-pair planes
    pack_w_kernel<<<(W11N + 255)/256, 256>>>(W11, p_w11p, p_w11p + W11N, NSEG, HID);
    pack_w_kernel<<<(W12N + 255)/256, 256>>>(W12, p_w12p, p_w12p + W12N, HID, NSEG);
    pack_w_kernel<<<(W11N + 255)/256, 256>>>(W21, p_w21p, p_w21p + W11N, NSEG, HID);
    pack_w_kernel<<<(W12N + 255)/256, 256>>>(W22, p_w22p, p_w22p + W12N, HID, NSEG);
    pack_w2_kernel<<<(512 * PREDL + 255)/256, 256>>>(Wtr, Wse, p_w2p, p_w2p + 512*PREDL);
    // 4) seasonal MLP (bf16x3 tensor-core GEMMs)
    bgemm_kernel<1,1><<<dim3(HID / 128, MMLP / 128), 256, SMEM_BYTES>>>(
        p_xsh, p_xsl, p_w11p, p_w11p + W11N, b11, nullptr, nullptr, p_hh, p_hl, MMLP, NSEG, HID);
    bgemm_kernel<0,1><<<dim3(1,         MMLP / 128), 256, SMEM_BYTES>>>(
        p_hh, p_hl, p_w12p, p_w12p + W12N, b12, nullptr, nullptr, p_xsh, p_xsl, MMLP, HID, NSEG);
    bgemm_kernel<1,1><<<dim3(HID / 128, MMLP / 128), 256, SMEM_BYTES>>>(
        p_xsh, p_xsl, p_w21p, p_w21p + W11N, b21, nullptr, nullptr, p_hh, p_hl, MMLP, NSEG, HID);
    bgemm_kernel<0,2><<<dim3(1,         MMLP / 128), 256, SMEM_BYTES>>>(
        p_hh, p_hl, p_w22p, p_w22p + W12N, b22, nullptr, nullptr, p_Abh, p_Abl, MMLP, HID, NSEG);
    // 5) fused heads: [trend|sea] @ [W_tr;W_se] (fp32 out)
    bgemm_kernel<0,0><<<dim3((PREDL + 127) / 128, BC / 128), 256, SMEM_BYTES>>>(
        p_Abh, p_Abl, p_w2p, p_w2p + 512*PREDL, btr, bse, p_y, nullptr, nullptr, BC, 1024, PREDL);
    // 6) denorm + transpose
    final_kernel<<<dim3((PREDL + 31) / 32, (CH + 31) / 32, BATCH), dim3(32, 32)>>>(rw, rb, out);
}

// round 11
// speedup vs baseline: 1.6594x; 1.0437x over previous
#include <cuda_runtime.h>
#include <cuda_bf16.h>
#include <math.h>
#include <stdint.h>

#define BATCH 128
#define SEQL  512
#define CH    321
#define PREDL 336
#define KWIN  25
#define NSEG  128          // SEQL / 4
#define HID   512
#define BC    (BATCH*CH)   // 41088
#define MMLP  (BC*4)       // 164352

typedef __nv_bfloat16 bf16;

// ---------------- static scratch (no allocation allowed) ----------------
__device__ float g_mean[BC];
__device__ float g_std [BC];
// bf16 hi/lo planes of activations (2 bytes each -> same traffic as fp32)
__device__ bf16  g_Abh [(size_t)BC*1024];        // [trend | sea-out] hi
__device__ bf16  g_Abl [(size_t)BC*1024];        // lo
__device__ bf16  g_xsh [(size_t)MMLP*NSEG];
__device__ bf16  g_xsl [(size_t)MMLP*NSEG];
__device__ bf16  g_hh  [(size_t)MMLP*HID];
__device__ bf16  g_hl  [(size_t)MMLP*HID];
// weights pre-packed as k-pair uint32 [(K/2) x N], hi/lo planes
__device__ uint32_t g_w11p[2][(NSEG/2)*HID];
__device__ uint32_t g_w12p[2][(HID/2)*NSEG];
__device__ uint32_t g_w21p[2][(NSEG/2)*HID];
__device__ uint32_t g_w22p[2][(HID/2)*NSEG];
__device__ uint32_t g_w2p [2][512*PREDL];        // concat [W_tr;W_se], K=1024
__device__ float g_y   [(size_t)BC*PREDL];

__device__ __forceinline__ void bsplit(float v, bf16& hi, bf16& lo) {
    hi = __float2bfloat16(v);
    lo = __float2bfloat16(v - __bfloat162float(hi));
}

// ---------------- stage 1: per-(b,c) mean / std over L ----------------
__global__ void stats_kernel(const float* __restrict__ x) {
    int c = blockIdx.x * 128 + threadIdx.x;
    int b = blockIdx.y;
    if (c >= CH) return;
    const float* p = x + (size_t)b * SEQL * CH + c;
    float s = 0.f, s2 = 0.f;
    #pragma unroll 4
    for (int l = 0; l < SEQL; ++l) {
        float v = p[(size_t)l * CH];
        s  += v;
        s2 += v * v;
    }
    float m   = s  * (1.0f / SEQL);
    float var = s2 * (1.0f / SEQL) - m * m;
    var = fmaxf(var, 0.0f);
    g_mean[b*CH + c] = m;
    g_std [b*CH + c] = sqrtf(var + 1e-5f);
}

// ---------------- stage 2+3 fused: normalize + decomp + interleave + split ----------------
#define NDC 16   // channels per block
__global__ __launch_bounds__(256)
void norm_decomp_kernel(const float* __restrict__ x,
                        const float* __restrict__ rw,
                        const float* __restrict__ rb) {
    __shared__ float sm[NDC][528];   // 528%32=16 -> the two ci-groups use disjoint bank halves
    int b  = blockIdx.y;
    int c0 = blockIdx.x * NDC;
    int tid = threadIdx.x;
    // load + normalize (coalesced over channels)
    for (int idx = tid; idx < NDC * SEQL; idx += 256) {
        int ci = idx & (NDC - 1), l = idx >> 4;
        int c = c0 + ci;
        float v = 0.f;
        if (c < CH) {
            float m  = g_mean[b*CH + c];
            float sd = g_std [b*CH + c];
            v = (x[((size_t)b * SEQL + l) * CH + c] - m) / sd * rw[c] + rb[c];
        }
        sm[ci][l] = v;
    }
    __syncthreads();
    int ci = tid >> 4;        // 0..15
    int lg = tid & 15;        // 0..15
    int c  = c0 + ci;
    if (c < CH) {
        int row = b*CH + c;
        #pragma unroll 4
        for (int i = 0; i < 32; ++i) {
            int l = lg + 16 * i;          // stride-16 l assignment: conflict-free window reads
            float v = sm[ci][l];
            float s = 0.f;
            #pragma unroll
            for (int d = -12; d <= 12; ++d) {
                int j = l + d;
                j = j < 0 ? 0 : (j > SEQL - 1 ? SEQL - 1 : j);
                s += sm[ci][j];
            }
            float trend = s * (1.0f / KWIN);
            float sea   = v - trend;
            bf16 th, tl, sh, sl;
            bsplit(trend, th, tl);
            bsplit(sea,   sh, sl);
            size_t ai = (size_t)row * 1024 + l;                         // head-A cols 0..511
            g_Abh[ai] = th;  g_Abl[ai] = tl;
            size_t si = ((size_t)row * 4 + (l & 3)) * NSEG + (l >> 2);  // xs[b,c,s,n]
            g_xsh[si] = sh;  g_xsl[si] = sl;
        }
    }
}

// ---------------- weight packing: [K][N] fp32 -> [K/2][N] uint32 pairs ----------------
__global__ void pack_w_kernel(const float* __restrict__ W,
                              uint32_t* __restrict__ Ph, uint32_t* __restrict__ Pl,
                              int Kd, int Nd) {
    int i = blockIdx.x * 256 + threadIdx.x;
    if (i >= (Kd / 2) * Nd) return;
    int kp = i / Nd, n = i - kp * Nd;
    float v0 = W[(size_t)(2 * kp)     * Nd + n];
    float v1 = W[(size_t)(2 * kp + 1) * Nd + n];
    bf16 h0, l0, h1, l1;
    bsplit(v0, h0, l0);
    bsplit(v1, h1, l1);
    Ph[i] = (uint32_t)__bfloat16_as_ushort(h0) | ((uint32_t)__bfloat16_as_ushort(h1) << 16);
    Pl[i] = (uint32_t)__bfloat16_as_ushort(l0) | ((uint32_t)__bfloat16_as_ushort(l1) << 16);
}
__global__ void pack_w2_kernel(const float* __restrict__ Wtr,
                               const float* __restrict__ Wse,
                               uint32_t* __restrict__ Ph, uint32_t* __restrict__ Pl) {
    int i = blockIdx.x * 256 + threadIdx.x;
    if (i >= 512 * PREDL) return;
    int kp = i / PREDL, n = i - kp * PREDL;
    int k0 = 2 * kp, k1 = 2 * kp + 1;   // both in same half (512-aligned)
    const float* src = (k0 < 512) ? Wtr : Wse;
    int kb = (k0 < 512) ? 0 : 512;
    float v0 = src[(size_t)(k0 - kb) * PREDL + n];
    float v1 = src[(size_t)(k1 - kb) * PREDL + n];
    bf16 h0, l0, h1, l1;
    bsplit(v0, h0, l0);
    bsplit(v1, h1, l1);
    Ph[i] = (uint32_t)__bfloat16_as_ushort(h0) | ((uint32_t)__bfloat16_as_ushort(h1) << 16);
    Pl[i] = (uint32_t)__bfloat16_as_ushort(l0) | ((uint32_t)__bfloat16_as_ushort(l1) << 16);
}

// ======================= bf16x3 tensor-core GEMM =======================
// C = act(A@B + bias [+bias2]) with A,B in (hi,lo) bf16 planes; fp32 accum.
// 128x128x32 tiles, 256 threads, 8 warps each 64x32 of m16n8k16 frags.
// Per k16-step: term-major over ALL 4 mt rows -> accumulator reuse distance
// 16 MMAs, with A-frag registers reused between hi and lo planes.

__device__ __forceinline__ void mma16(float4& d, uint32_t a0, uint32_t a1,
                                      uint32_t a2, uint32_t a3,
                                      uint32_t b0, uint32_t b1) {
    asm volatile(
        "mma.sync.aligned.m16n8k16.row.col.f32.bf16.bf16.f32 "
        "{%0,%1,%2,%3},{%4,%5,%6,%7},{%8,%9},{%0,%1,%2,%3};"
        : "+f"(d.x), "+f"(d.y), "+f"(d.z), "+f"(d.w)
        : "r"(a0), "r"(a1), "r"(a2), "r"(a3), "r"(b0), "r"(b1));
}
__device__ __forceinline__ void cp16(uint32_t dst, const void* src, int bytes) {
    asm volatile("cp.async.cg.shared.global [%0], [%1], 16, %2;\n"
                 :: "r"(dst), "l"(src), "r"(bytes));
}

#define BKT 32     // k-depth per tile (elements)
#define PA  20     // A smem row stride in words (16 used)  -> conflict-free
#define PB  136    // B smem row stride in words (128 used) -> conflict-free
#define AS_WORDS (2*2*128*PA)              // 10240
#define BS_WORDS (2*2*16*PB)               // 8704
#define SMEM_BYTES ((AS_WORDS+BS_WORDS)*4) // 75776

// MODE: 0 = fp32 out; 1 = bf16 hi/lo out; 2 = bf16 hi/lo + interleave into A
template<int GELU, int MODE>
__global__ __launch_bounds__(256)
void bgemm_kernel(const bf16* __restrict__ Ah_, const bf16* __restrict__ Al_,
                  const uint32_t* __restrict__ Bhp, const uint32_t* __restrict__ Blp,
                  const float* __restrict__ bias, const float* __restrict__ bias2,
                  float* __restrict__ Cf, bf16* __restrict__ Chb, bf16* __restrict__ Clb,
                  int M, int Kd, int Nd) {
    extern __shared__ uint32_t smw[];
    uint32_t* Asw = smw;              // [2buf][2pl][128][PA]
    uint32_t* Bsw = smw + AS_WORDS;   // [2buf][2pl][16][PB]

    const int tid  = threadIdx.x;
    const int lane = tid & 31, wid = tid >> 5;
    const int gid  = lane >> 2, tig = lane & 3;
    const int wm   = (wid & 1) * 64;
    const int wn   = (wid >> 1) * 32;
    const int m0   = blockIdx.y * 128;
    const int n0   = blockIdx.x * 128;

    const uint32_t As_base = (uint32_t)__cvta_generic_to_shared(Asw);
    const uint32_t Bs_base = (uint32_t)__cvta_generic_to_shared(Bsw);

    float4 acc[4][4];
    #pragma unroll
    for (int i = 0; i < 4; ++i)
        #pragma unroll
        for (int j = 0; j < 4; ++j) acc[i][j] = make_float4(0.f, 0.f, 0.f, 0.f);

    auto fill = [&](int t, int buf) {
        const int k0 = t * BKT;
        // A: 2 planes x 128 rows x 4 chunks(16B=8 bf16) = 1024 chunks
        #pragma unroll
        for (int i = 0; i < 4; ++i) {
            int c = tid + 256 * i;
            int pl = c >> 9, rr = (c >> 2) & 127, ch = c & 3;
            const bf16* src = (pl ? Al_ : Ah_) + (size_t)(m0 + rr) * Kd + k0 + ch * 8;
            uint32_t dst = As_base + (uint32_t)(((((buf*2+pl)*128 + rr) * PA) + ch * 4) * 4);
            cp16(dst, src, 16);
        }
        // B: 2 planes x 16 kpairs x 32 chunks(16B=4 n-words) = 1024 chunks
        #pragma unroll
        for (int i = 0; i < 4; ++i) {
            int c = tid + 256 * i;
            int pl = c >> 9, kp = (c >> 5) & 15, ch = c & 31;
            int bn = n0 + ch * 4;
            int bytes = (Nd - bn) * 4;
            bytes = bytes < 0 ? 0 : (bytes > 16 ? 16 : bytes);
            const uint32_t* src = (pl ? Blp : Bhp) + (size_t)(k0/2 + kp) * Nd + (bytes > 0 ? bn : 0);
            uint32_t dst = Bs_base + (uint32_t)(((((buf*2+pl)*16 + kp) * PB) + ch * 4) * 4);
            cp16(dst, src, bytes);
        }
    };

    fill(0, 0);
    asm volatile("cp.async.commit_group;");
    asm volatile("cp.async.wait_group 0;");
    __syncthreads();

    const int nk = Kd / BKT;
    for (int t = 0; t < nk; ++t) {
        const int buf = t & 1;
        if (t + 1 < nk) {
            fill(t + 1, buf ^ 1);
            asm volatile("cp.async.commit_group;");
        }
        #pragma unroll
        for (int kk2 = 0; kk2 < 16; kk2 += 8) {      // two k16-steps per tile
            uint32_t bh[4][2], bl[4][2];
            #pragma unroll
            for (int nt = 0; nt < 4; ++nt) {
                int col = wn + nt * 8 + gid;
                bh[nt][0] = Bsw[((buf*2+0)*16 + kk2 + tig    ) * PB + col];
                bh[nt][1] = Bsw[((buf*2+0)*16 + kk2 + tig + 4) * PB + col];
                bl[nt][0] = Bsw[((buf*2+1)*16 + kk2 + tig    ) * PB + col];
                bl[nt][1] = Bsw[((buf*2+1)*16 + kk2 + tig + 4) * PB + col];
            }
            uint32_t af[4][4];
            // ---- load A hi-plane frags for all 4 mt rows ----
            #pragma unroll
            for (int mt = 0; mt < 4; ++mt) {
                int r0 = wm + mt * 16 + gid;
                af[mt][0] = Asw[((buf*2+0)*128 + r0    ) * PA + kk2 + tig    ];
                af[mt][1] = Asw[((buf*2+0)*128 + r0 + 8) * PA + kk2 + tig    ];
                af[mt][2] = Asw[((buf*2+0)*128 + r0    ) * PA + kk2 + tig + 4];
                af[mt][3] = Asw[((buf*2+0)*128 + r0 + 8) * PA + kk2 + tig + 4];
            }
            // term 0: ah * bh   (reuse distance 16 MMAs per accumulator)
            #pragma unroll
            for (int mt = 0; mt < 4; ++mt)
                #pragma unroll
                for (int nt = 0; nt < 4; ++nt)
                    mma16(acc[mt][nt], af[mt][0], af[mt][1], af[mt][2], af[mt][3],
                          bh[nt][0], bh[nt][1]);
            // term 1: ah * bl
            #pragma unroll
            for (int mt = 0; mt < 4; ++mt)
                #pragma unroll
                for (int nt = 0; nt < 4; ++nt)
                    mma16(acc[mt][nt], af[mt][0], af[mt][1], af[mt][2], af[mt][3],
                          bl[nt][0], bl[nt][1]);
            // ---- overwrite with A lo-plane frags (register reuse) ----
            #pragma unroll
            for (int mt = 0; mt < 4; ++mt) {
                int r0 = wm + mt * 16 + gid;
                af[mt][0] = Asw[((buf*2+1)*128 + r0    ) * PA + kk2 + tig    ];
                af[mt][1] = Asw[((buf*2+1)*128 + r0 + 8) * PA + kk2 + tig    ];
                af[mt][2] = Asw[((buf*2+1)*128 + r0    ) * PA + kk2 + tig + 4];
                af[mt][3] = Asw[((buf*2+1)*128 + r0 + 8) * PA + kk2 + tig + 4];
            }
            // term 2: al * bh
            #pragma unroll
            for (int mt = 0; mt < 4; ++mt)
                #pragma unroll
                for (int nt = 0; nt < 4; ++nt)
                    mma16(acc[mt][nt], af[mt][0], af[mt][1], af[mt][2], af[mt][3],
                          bh[nt][0], bh[nt][1]);
        }
        if (t + 1 < nk) asm volatile("cp.async.wait_group 0;");
        __syncthreads();
    }

    // epilogue
    auto emit = [&](int row, int col, float v) {
        if (col >= Nd) return;
        v += bias[col];
        if (bias2) v += bias2[col];
        if (GELU)  v = 0.5f * v * (1.0f + erff(v * 0.70710678118654752f));
        if (MODE == 0) {
            Cf[(size_t)row * Nd + col] = v;
        } else {
            bf16 h, l2;
            bsplit(v, h, l2);
            size_t idx = (MODE == 2)
                ? ((size_t)(row >> 2)) * 1024 + 512 + (size_t)col * 4 + (row & 3)
                : (size_t)row * Nd + col;
            Chb[idx] = h;
            Clb[idx] = l2;
        }
    };
    #pragma unroll
    for (int mt = 0; mt < 4; ++mt) {
        int r0 = m0 + wm + mt * 16 + gid;
        #pragma unroll
        for (int nt = 0; nt < 4; ++nt) {
            int c0 = n0 + wn + nt * 8 + 2 * tig;
            float4 c = acc[mt][nt];
            emit(r0,     c0,     c.x);
            emit(r0,     c0 + 1, c.y);
            emit(r0 + 8, c0,     c.z);
            emit(r0 + 8, c0 + 1, c.w);
        }
    }
}

// ---------------- final: denorm + transpose to [B, PRED, C] ----------------
__global__ void final_kernel(const float* __restrict__ rw,
                             const float* __restrict__ rb,
                             float* __restrict__ out) {
    __shared__ float sm[32][33];
    int b  = blockIdx.z;
    int p0 = blockIdx.x * 32, c0 = blockIdx.y * 32;
    int tx = threadIdx.x, ty = threadIdx.y;
    int p = p0 + tx, c = c0 + ty;
    if (p < PREDL && c < CH)
        sm[ty][tx] = g_y[((size_t)(b*CH + c)) * PREDL + p];
    __syncthreads();
    int cw = c0 + tx, pw = p0 + ty;
    if (cw < CH && pw < PREDL) {
        float v = sm[tx][ty];
        v = (v - rb[cw]) / (rw[cw] + 1e-10f);
        v = v * g_std[b*CH + cw] + g_mean[b*CH + cw];
        out[((size_t)b * PREDL + pw) * CH + cw] = v;
    }
}

// ---------------- launch ----------------
extern "C" void kernel_launch(void* const* d_in, const int* in_sizes, int n_in,
                              void* d_out, int out_size) {
    const float* x   = (const float*)d_in[0];
    const float* rw  = (const float*)d_in[1];
    const float* rb  = (const float*)d_in[2];
    const float* W11 = (const float*)d_in[3];
    const float* b11 = (const float*)d_in[4];
    const float* W12 = (const float*)d_in[5];
    const float* b12 = (const float*)d_in[6];
    const float* W21 = (const float*)d_in[7];
    const float* b21 = (const float*)d_in[8];
    const float* W22 = (const float*)d_in[9];
    const float* b22 = (const float*)d_in[10];
    const float* Wtr = (const float*)d_in[11];
    const float* btr = (const float*)d_in[12];
    const float* Wse = (const float*)d_in[13];
    const float* bse = (const float*)d_in[14];
    float* out = (float*)d_out;
    (void)in_sizes; (void)n_in; (void)out_size;

    bf16 *p_Abh, *p_Abl, *p_xsh, *p_xsl, *p_hh, *p_hl;
    uint32_t *p_w11p, *p_w12p, *p_w21p, *p_w22p, *p_w2p;
    float *p_y;
    cudaGetSymbolAddress((void**)&p_Abh, g_Abh); cudaGetSymbolAddress((void**)&p_Abl, g_Abl);
    cudaGetSymbolAddress((void**)&p_xsh, g_xsh); cudaGetSymbolAddress((void**)&p_xsl, g_xsl);
    cudaGetSymbolAddress((void**)&p_hh,  g_hh);  cudaGetSymbolAddress((void**)&p_hl,  g_hl);
    cudaGetSymbolAddress((void**)&p_w11p, g_w11p);
    cudaGetSymbolAddress((void**)&p_w12p, g_w12p);
    cudaGetSymbolAddress((void**)&p_w21p, g_w21p);
    cudaGetSymbolAddress((void**)&p_w22p, g_w22p);
    cudaGetSymbolAddress((void**)&p_w2p,  g_w2p);
    cudaGetSymbolAddress((void**)&p_y,    g_y);

    cudaFuncSetAttribute(bgemm_kernel<1,1>, cudaFuncAttributeMaxDynamicSharedMemorySize, SMEM_BYTES);
    cudaFuncSetAttribute(bgemm_kernel<0,1>, cudaFuncAttributeMaxDynamicSharedMemorySize, SMEM_BYTES);
    cudaFuncSetAttribute(bgemm_kernel<0,2>, cudaFuncAttributeMaxDynamicSharedMemorySize, SMEM_BYTES);
    cudaFuncSetAttribute(bgemm_kernel<0,0>, cudaFuncAttributeMaxDynamicSharedMemorySize, SMEM_BYTES);

    const int W11N = (NSEG/2)*HID, W12N = (HID/2)*NSEG;

    // 1) RevIN statistics
    stats_kernel<<<dim3((CH + 127) / 128, BATCH), 128>>>(x);
    // 2+3) fused normalize + decomposition (+ bf16 split, interleave)
    norm_decomp_kernel<<<dim3((CH + NDC - 1) / NDC, BATCH), 256>>>(x, rw, rb);
    // 3b) pack weights into bf16 k-pair planes
    pack_w_kernel<<<(W11N + 255)/256, 256>>>(W11, p_w11p, p_w11p + W11N, NSEG, HID);
    pack_w_kernel<<<(W12N + 255)/256, 256>>>(W12, p_w12p, p_w12p + W12N, HID, NSEG);
    pack_w_kernel<<<(W11N + 255)/256, 256>>>(W21, p_w21p, p_w21p + W11N, NSEG, HID);
    pack_w_kernel<<<(W12N + 255)/256, 256>>>(W22, p_w22p, p_w22p + W12N, HID, NSEG);
    pack_w2_kernel<<<(512 * PREDL + 255)/256, 256>>>(Wtr, Wse, p_w2p, p_w2p + 512*PREDL);
    // 4) seasonal MLP (bf16x3 tensor-core GEMMs)
    bgemm_kernel<1,1><<<dim3(HID / 128, MMLP / 128), 256, SMEM_BYTES>>>(
        p_xsh, p_xsl, p_w11p, p_w11p + W11N, b11, nullptr, nullptr, p_hh, p_hl, MMLP, NSEG, HID);
    bgemm_kernel<0,1><<<dim3(1,         MMLP / 128), 256, SMEM_BYTES>>>(
        p_hh, p_hl, p_w12p, p_w12p + W12N, b12, nullptr, nullptr, p_xsh, p_xsl, MMLP, HID, NSEG);
    bgemm_kernel<1,1><<<dim3(HID / 128, MMLP / 128), 256, SMEM_BYTES>>>(
        p_xsh, p_xsl, p_w21p, p_w21p + W11N, b21, nullptr, nullptr, p_hh, p_hl, MMLP, NSEG, HID);
    bgemm_kernel<0,2><<<dim3(1,         MMLP / 128), 256, SMEM_BYTES>>>(
        p_hh, p_hl, p_w22p, p_w22p + W12N, b22, nullptr, nullptr, p_Abh, p_Abl, MMLP, HID, NSEG);
    // 5) fused heads: [trend|sea] @ [W_tr;W_se] (fp32 out)
    bgemm_kernel<0,0><<<dim3((PREDL + 127) / 128, BC / 128), 256, SMEM_BYTES>>>(
        p_Abh, p_Abl, p_w2p, p_w2p + 512*PREDL, btr, bse, p_y, nullptr, nullptr, BC, 1024, PREDL);
    // 6) denorm + transpose
    final_kernel<<<dim3((PREDL + 31) / 32, (CH + 31) / 32, BATCH), dim3(32, 32)>>>(rw, rb, out);
}

// round 12
// speedup vs baseline: 2.1483x; 1.2946x over previous
#include <cuda_runtime.h>
#include <cuda_bf16.h>
#include <math.h>
#include <stdint.h>

#define BATCH 128
#define SEQL  512
#define CH    321
#define PREDL 336
#define KWIN  25
#define NSEG  128          // SEQL / 4
#define HID   512
#define BC    (BATCH*CH)   // 41088
#define MMLP  (BC*4)       // 164352

typedef __nv_bfloat16 bf16;

// ---------------- static scratch (no allocation allowed) ----------------
__device__ float g_mean[BC];
__device__ float g_std [BC];
__device__ bf16  g_Abh [(size_t)BC*1024];        // [trend | sea-out] hi
__device__ bf16  g_Abl [(size_t)BC*1024];        // lo
__device__ bf16  g_xsh [(size_t)MMLP*NSEG];
__device__ bf16  g_xsl [(size_t)MMLP*NSEG];
__device__ bf16  g_hh  [(size_t)MMLP*HID];
__device__ bf16  g_hl  [(size_t)MMLP*HID];
// weights packed N-MAJOR: [N][K/2] uint32 (bf16 k-pairs), hi plane then lo plane
__device__ uint32_t g_w11p[2][HID*(NSEG/2)];
__device__ uint32_t g_w12p[2][NSEG*(HID/2)];
__device__ uint32_t g_w21p[2][HID*(NSEG/2)];
__device__ uint32_t g_w22p[2][NSEG*(HID/2)];
__device__ uint32_t g_w2p [2][PREDL*512];        // concat [W_tr;W_se], K=1024
__device__ float g_y   [(size_t)BC*PREDL];

__device__ __forceinline__ void bsplit(float v, bf16& hi, bf16& lo) {
    hi = __float2bfloat16(v);
    lo = __float2bfloat16(v - __bfloat162float(hi));
}
__device__ __forceinline__ uint32_t bpack(bf16 a, bf16 b) {
    return (uint32_t)__bfloat16_as_ushort(a) | ((uint32_t)__bfloat16_as_ushort(b) << 16);
}

// ---------------- stage 1: per-(b,c) mean / std over L ----------------
__global__ void stats_kernel(const float* __restrict__ x) {
    int c = blockIdx.x * 128 + threadIdx.x;
    int b = blockIdx.y;
    if (c >= CH) return;
    const float* p = x + (size_t)b * SEQL * CH + c;
    float s = 0.f, s2 = 0.f;
    #pragma unroll 4
    for (int l = 0; l < SEQL; ++l) {
        float v = p[(size_t)l * CH];
        s  += v;
        s2 += v * v;
    }
    float m   = s  * (1.0f / SEQL);
    float var = s2 * (1.0f / SEQL) - m * m;
    var = fmaxf(var, 0.0f);
    g_mean[b*CH + c] = m;
    g_std [b*CH + c] = sqrtf(var + 1e-5f);
}

// ---------------- stage 2+3 fused: normalize + decomp + interleave + split ----------------
#define NDC 16   // channels per block
__global__ __launch_bounds__(256)
void norm_decomp_kernel(const float* __restrict__ x,
                        const float* __restrict__ rw,
                        const float* __restrict__ rb) {
    __shared__ float sm[NDC][528];
    int b  = blockIdx.y;
    int c0 = blockIdx.x * NDC;
    int tid = threadIdx.x;
    for (int idx = tid; idx < NDC * SEQL; idx += 256) {
        int ci = idx & (NDC - 1), l = idx >> 4;
        int c = c0 + ci;
        float v = 0.f;
        if (c < CH) {
            float m  = g_mean[b*CH + c];
            float sd = g_std [b*CH + c];
            v = (x[((size_t)b * SEQL + l) * CH + c] - m) / sd * rw[c] + rb[c];
        }
        sm[ci][l] = v;
    }
    __syncthreads();
    int ci = tid >> 4;
    int lg = tid & 15;
    int c  = c0 + ci;
    if (c < CH) {
        int row = b*CH + c;
        #pragma unroll 4
        for (int i = 0; i < 32; ++i) {
            int l = lg + 16 * i;
            float v = sm[ci][l];
            float s = 0.f;
            #pragma unroll
            for (int d = -12; d <= 12; ++d) {
                int j = l + d;
                j = j < 0 ? 0 : (j > SEQL - 1 ? SEQL - 1 : j);
                s += sm[ci][j];
            }
            float trend = s * (1.0f / KWIN);
            float sea   = v - trend;
            bf16 th, tl, sh, sl;
            bsplit(trend, th, tl);
            bsplit(sea,   sh, sl);
            size_t ai = (size_t)row * 1024 + l;
            g_Abh[ai] = th;  g_Abl[ai] = tl;
            size_t si = ((size_t)row * 4 + (l & 3)) * NSEG + (l >> 2);
            g_xsh[si] = sh;  g_xsl[si] = sl;
        }
    }
}

// ---------------- weight packing: [K][N] fp32 -> N-major [N][K/2] u32 pairs ----------------
__global__ void pack_w_kernel(const float* __restrict__ W,
                              uint32_t* __restrict__ Ph, uint32_t* __restrict__ Pl,
                              int Kd, int Nd) {
    int i = blockIdx.x * 256 + threadIdx.x;       // i = n*(Kd/2) + kp
    if (i >= Nd * (Kd / 2)) return;
    int n = i / (Kd / 2), kp = i - n * (Kd / 2);
    float v0 = W[(size_t)(2 * kp)     * Nd + n];
    float v1 = W[(size_t)(2 * kp + 1) * Nd + n];
    bf16 h0, l0, h1, l1;
    bsplit(v0, h0, l0);
    bsplit(v1, h1, l1);
    Ph[i] = bpack(h0, h1);
    Pl[i] = bpack(l0, l1);
}
__global__ void pack_w2_kernel(const float* __restrict__ Wtr,
                               const float* __restrict__ Wse,
                               uint32_t* __restrict__ Ph, uint32_t* __restrict__ Pl) {
    int i = blockIdx.x * 256 + threadIdx.x;       // i = n*512 + kp, K=1024
    if (i >= PREDL * 512) return;
    int n = i >> 9, kp = i & 511;
    int k0 = 2 * kp;
    const float* src = (k0 < 512) ? Wtr : Wse;
    int kb = (k0 < 512) ? 0 : 512;
    float v0 = src[(size_t)(k0 - kb)     * PREDL + n];
    float v1 = src[(size_t)(k0 - kb + 1) * PREDL + n];
    bf16 h0, l0, h1, l1;
    bsplit(v0, h0, l0);
    bsplit(v1, h1, l1);
    Ph[i] = bpack(h0, h1);
    Pl[i] = bpack(l0, l1);
}

// ======================= bf16x3 tensor-core GEMM (ldmatrix) =======================
__device__ __forceinline__ void mma16(float4& d, uint32_t a0, uint32_t a1,
                                      uint32_t a2, uint32_t a3,
                                      uint32_t b0, uint32_t b1) {
    asm volatile(
        "mma.sync.aligned.m16n8k16.row.col.f32.bf16.bf16.f32 "
        "{%0,%1,%2,%3},{%4,%5,%6,%7},{%8,%9},{%0,%1,%2,%3};"
        : "+f"(d.x), "+f"(d.y), "+f"(d.z), "+f"(d.w)
        : "r"(a0), "r"(a1), "r"(a2), "r"(a3), "r"(b0), "r"(b1));
}
__device__ __forceinline__ void cp16(uint32_t dst, const void* src, int bytes) {
    asm volatile("cp.async.cg.shared.global [%0], [%1], 16, %2;\n"
                 :: "r"(dst), "l"(src), "r"(bytes));
}
__device__ __forceinline__ void ldsm4(uint32_t& r0, uint32_t& r1, uint32_t& r2,
                                      uint32_t& r3, uint32_t addr) {
    asm volatile("ldmatrix.sync.aligned.m8n8.x4.shared.b16 {%0,%1,%2,%3}, [%4];"
                 : "=r"(r0), "=r"(r1), "=r"(r2), "=r"(r3) : "r"(addr));
}

#define BKT 32     // k-depth per tile (elements) = 16 kpair words
#define PA  20     // A smem row stride (words); stride-20 rows -> conflict-free LDSM
#define PBK 20     // B smem row stride (words), n-major rows of 16 kpair words
#define AS_WORDS (2*2*128*PA)               // 10240
#define BS_WORDS (2*2*128*PBK)              // 10240
#define SMEM_BYTES ((AS_WORDS+BS_WORDS)*4)  // 81920

// MODE: 0 = fp32 out; 1 = bf16 hi/lo out; 2 = bf16 hi/lo + interleave into A
template<int GELU, int MODE>
__global__ __launch_bounds__(256, 2)
void bgemm_kernel(const bf16* __restrict__ Ah_, const bf16* __restrict__ Al_,
                  const uint32_t* __restrict__ Bhp, const uint32_t* __restrict__ Blp,
                  const float* __restrict__ bias, const float* __restrict__ bias2,
                  float* __restrict__ Cf, bf16* __restrict__ Chb, bf16* __restrict__ Clb,
                  int M, int Kd, int Nd) {
    extern __shared__ uint32_t smw[];
    uint32_t* Asw = smw;              // [2buf][2pl][128][PA]
    uint32_t* Bsw = smw + AS_WORDS;   // [2buf][2pl][128 n][PBK]

    const int tid  = threadIdx.x;
    const int lane = tid & 31, wid = tid >> 5;
    const int gid  = lane >> 2, tig = lane & 3;
    const int wm   = (wid & 1) * 64;
    const int wn   = (wid >> 1) * 32;
    const int m0   = blockIdx.y * 128;
    const int n0   = blockIdx.x * 128;
    const bool wactive = (n0 + wn) < Nd;

    const uint32_t As_base = (uint32_t)__cvta_generic_to_shared(Asw);
    const uint32_t Bs_base = (uint32_t)__cvta_generic_to_shared(Bsw);

    // ldmatrix per-thread row/word offsets
    const int a_rowl = wm + (lane & 15);
    const int a_koff = (lane >> 4) * 4;
    const int b_rowl = wn + (lane & 7) + ((lane >> 4) << 3);
    const int b_koff = ((lane >> 3) & 1) * 4;

    float4 acc[4][4];
    #pragma unroll
    for (int i = 0; i < 4; ++i)
        #pragma unroll
        for (int j = 0; j < 4; ++j) acc[i][j] = make_float4(0.f, 0.f, 0.f, 0.f);

    auto fill = [&](int t, int buf) {
        const int k0 = t * BKT;
        // A: 2 planes x 128 rows x 4 chunks(16B = 8 bf16)
        #pragma unroll
        for (int i = 0; i < 4; ++i) {
            int c = tid + 256 * i;
            int pl = c >> 9, rr = (c >> 2) & 127, ch = c & 3;
            const bf16* src = (pl ? Al_ : Ah_) + (size_t)(m0 + rr) * Kd + k0 + ch * 8;
            uint32_t dst = As_base + (uint32_t)(((((buf*2+pl)*128 + rr) * PA) + ch * 4) * 4);
            cp16(dst, src, 16);
        }
        // B (n-major): 2 planes x 128 n-rows x 4 chunks of 4 kpair-words
        #pragma unroll
        for (int i = 0; i < 4; ++i) {
            int c = tid + 256 * i;
            int pl = c >> 9, rr = (c >> 2) & 127, ch = c & 3;
            int n = n0 + rr;
            const uint32_t* base = pl ? Blp : Bhp;
            const uint32_t* src = base;
            int bytes = 0;
            if (n < Nd) { src = base + (size_t)n * (Kd/2) + k0/2 + ch * 4; bytes = 16; }
            uint32_t dst = Bs_base + (uint32_t)(((((buf*2+pl)*128 + rr) * PBK) + ch * 4) * 4);
            cp16(dst, src, bytes);
        }
    };

    fill(0, 0);
    asm volatile("cp.async.commit_group;");
    asm volatile("cp.async.wait_group 0;");
    __syncthreads();

    const int nk = Kd / BKT;
    for (int t = 0; t < nk; ++t) {
        const int buf = t & 1;
        if (t + 1 < nk) {
            fill(t + 1, buf ^ 1);
            asm volatile("cp.async.commit_group;");
        }
        if (wactive) {
            #pragma unroll
            for (int kk2 = 0; kk2 < 16; kk2 += 8) {
                const uint32_t aoff_hi = As_base +
                    (uint32_t)(((((buf*2+0)*128 + a_rowl) * PA) + kk2 + a_koff) * 4);
                const uint32_t boff_hi = Bs_base +
                    (uint32_t)(((((buf*2+0)*128 + b_rowl) * PBK) + kk2 + b_koff) * 4);
                const uint32_t aoff_lo = aoff_hi + (uint32_t)(128 * PA * 4);
                const uint32_t boff_lo = boff_hi + (uint32_t)(128 * PBK * 4);

                uint32_t bh[4][2], bl[4][2], af[4][4];
                ldsm4(bh[0][0], bh[0][1], bh[1][0], bh[1][1], boff_hi);
                ldsm4(bh[2][0], bh[2][1], bh[3][0], bh[3][1], boff_hi + 16*PBK*4);
                ldsm4(bl[0][0], bl[0][1], bl[1][0], bl[1][1], boff_lo);
                ldsm4(bl[2][0], bl[2][1], bl[3][0], bl[3][1], boff_lo + 16*PBK*4);
                #pragma unroll
                for (int mt = 0; mt < 4; ++mt)
                    ldsm4(af[mt][0], af[mt][1], af[mt][2], af[mt][3],
                          aoff_hi + mt * 16*PA*4);
                // term 0: ah * bh  (acc reuse distance 16)
                #pragma unroll
                for (int mt = 0; mt < 4; ++mt)
                    #pragma unroll
                    for (int nt = 0; nt < 4; ++nt)
                        mma16(acc[mt][nt], af[mt][0], af[mt][1], af[mt][2], af[mt][3],
                              bh[nt][0], bh[nt][1]);
                // term 1: ah * bl
                #pragma unroll
                for (int mt = 0; mt < 4; ++mt)
                    #pragma unroll
                    for (int nt = 0; nt < 4; ++nt)
                        mma16(acc[mt][nt], af[mt][0], af[mt][1], af[mt][2], af[mt][3],
                              bl[nt][0], bl[nt][1]);
                // reload A frags from lo plane
                #pragma unroll
                for (int mt = 0; mt < 4; ++mt)
                    ldsm4(af[mt][0], af[mt][1], af[mt][2], af[mt][3],
                          aoff_lo + mt * 16*PA*4);
                // term 2: al * bh
                #pragma unroll
                for (int mt = 0; mt < 4; ++mt)
                    #pragma unroll
                    for (int nt = 0; nt < 4; ++nt)
                        mma16(acc[mt][nt], af[mt][0], af[mt][1], af[mt][2], af[mt][3],
                              bh[nt][0], bh[nt][1]);
            }
        }
        if (t + 1 < nk) asm volatile("cp.async.wait_group 0;");
        __syncthreads();
    }

    // epilogue (paired stores; col even, Nd even)
    auto emit2 = [&](int row, int col, float v0, float v1) {
        if (col >= Nd) return;
        v0 += bias[col]; v1 += bias[col + 1];
        if (bias2) { v0 += bias2[col]; v1 += bias2[col + 1]; }
        if (GELU) {
            v0 = 0.5f * v0 * (1.0f + erff(v0 * 0.70710678118654752f));
            v1 = 0.5f * v1 * (1.0f + erff(v1 * 0.70710678118654752f));
        }
        if (MODE == 0) {
            *reinterpret_cast<float2*>(&Cf[(size_t)row * Nd + col]) = make_float2(v0, v1);
        } else if (MODE == 1) {
            bf16 h0, l0, h1, l1;
            bsplit(v0, h0, l0);
            bsplit(v1, h1, l1);
            *reinterpret_cast<uint32_t*>(&Chb[(size_t)row * Nd + col]) = bpack(h0, h1);
            *reinterpret_cast<uint32_t*>(&Clb[(size_t)row * Nd + col]) = bpack(l0, l1);
        } else {
            bf16 h0, l0, h1, l1;
            bsplit(v0, h0, l0);
            bsplit(v1, h1, l1);
            size_t i0 = ((size_t)(row >> 2)) * 1024 + 512 + (size_t)col * 4 + (row & 3);
            Chb[i0] = h0;       Clb[i0] = l0;
            Chb[i0 + 4] = h1;   Clb[i0 + 4] = l1;
        }
    };
    #pragma unroll
    for (int mt = 0; mt < 4; ++mt) {
        int r0 = m0 + wm + mt * 16 + gid;
        #pragma unroll
        for (int nt = 0; nt < 4; ++nt) {
            int c0 = n0 + wn + nt * 8 + 2 * tig;
            float4 c = acc[mt][nt];
            emit2(r0,     c0, c.x, c.y);
            emit2(r0 + 8, c0, c.z, c.w);
        }
    }
}

// ---------------- final: denorm + transpose to [B, PRED, C] ----------------
__global__ void final_kernel(const float* __restrict__ rw,
                             const float* __restrict__ rb,
                             float* __restrict__ out) {
    __shared__ float sm[32][33];
    int b  = blockIdx.z;
    int p0 = blockIdx.x * 32, c0 = blockIdx.y * 32;
    int tx = threadIdx.x, ty = threadIdx.y;
    int p = p0 + tx, c = c0 + ty;
    if (p < PREDL && c < CH)
        sm[ty][tx] = g_y[((size_t)(b*CH + c)) * PREDL + p];
    __syncthreads();
    int cw = c0 + tx, pw = p0 + ty;
    if (cw < CH && pw < PREDL) {
        float v = sm[tx][ty];
        v = (v - rb[cw]) / (rw[cw] + 1e-10f);
        v = v * g_std[b*CH + cw] + g_mean[b*CH + cw];
        out[((size_t)b * PREDL + pw) * CH + cw] = v;
    }
}

// ---------------- launch ----------------
extern "C" void kernel_launch(void* const* d_in, const int* in_sizes, int n_in,
                              void* d_out, int out_size) {
    const float* x   = (const float*)d_in[0];
    const float* rw  = (const float*)d_in[1];
    const float* rb  = (const float*)d_in[2];
    const float* W11 = (const float*)d_in[3];
    const float* b11 = (const float*)d_in[4];
    const float* W12 = (const float*)d_in[5];
    const float* b12 = (const float*)d_in[6];
    const float* W21 = (const float*)d_in[7];
    const float* b21 = (const float*)d_in[8];
    const float* W22 = (const float*)d_in[9];
    const float* b22 = (const float*)d_in[10];
    const float* Wtr = (const float*)d_in[11];
    const float* btr = (const float*)d_in[12];
    const float* Wse = (const float*)d_in[13];
    const float* bse = (const float*)d_in[14];
    float* out = (float*)d_out;
    (void)in_sizes; (void)n_in; (void)out_size;

    bf16 *p_Abh, *p_Abl, *p_xsh, *p_xsl, *p_hh, *p_hl;
    uint32_t *p_w11p, *p_w12p, *p_w21p, *p_w22p, *p_w2p;
    float *p_y;
    cudaGetSymbolAddress((void**)&p_Abh, g_Abh); cudaGetSymbolAddress((void**)&p_Abl, g_Abl);
    cudaGetSymbolAddress((void**)&p_xsh, g_xsh); cudaGetSymbolAddress((void**)&p_xsl, g_xsl);
    cudaGetSymbolAddress((void**)&p_hh,  g_hh);  cudaGetSymbolAddress((void**)&p_hl,  g_hl);
    cudaGetSymbolAddress((void**)&p_w11p, g_w11p);
    cudaGetSymbolAddress((void**)&p_w12p, g_w12p);
    cudaGetSymbolAddress((void**)&p_w21p, g_w21p);
    cudaGetSymbolAddress((void**)&p_w22p, g_w22p);
    cudaGetSymbolAddress((void**)&p_w2p,  g_w2p);
    cudaGetSymbolAddress((void**)&p_y,    g_y);

    cudaFuncSetAttribute(bgemm_kernel<1,1>, cudaFuncAttributeMaxDynamicSharedMemorySize, SMEM_BYTES);
    cudaFuncSetAttribute(bgemm_kernel<0,1>, cudaFuncAttributeMaxDynamicSharedMemorySize, SMEM_BYTES);
    cudaFuncSetAttribute(bgemm_kernel<0,2>, cudaFuncAttributeMaxDynamicSharedMemorySize, SMEM_BYTES);
    cudaFuncSetAttribute(bgemm_kernel<0,0>, cudaFuncAttributeMaxDynamicSharedMemorySize, SMEM_BYTES);

    const int W11N = HID*(NSEG/2), W12N = NSEG*(HID/2);

    // 1) RevIN statistics
    stats_kernel<<<dim3((CH + 127) / 128, BATCH), 128>>>(x);
    // 2+3) fused normalize + decomposition (+ bf16 split, interleave)
    norm_decomp_kernel<<<dim3((CH + NDC - 1) / NDC, BATCH), 256>>>(x, rw, rb);
    // 3b) pack weights into N-major bf16 k-pair planes
    pack_w_kernel<<<(W11N + 255)/256, 256>>>(W11, p_w11p, p_w11p + W11N, NSEG, HID);
    pack_w_kernel<<<(W12N + 255)/256, 256>>>(W12, p_w12p, p_w12p + W12N, HID, NSEG);
    pack_w_kernel<<<(W11N + 255)/256, 256>>>(W21, p_w21p, p_w21p + W11N, NSEG, HID);
    pack_w_kernel<<<(W12N + 255)/256, 256>>>(W22, p_w22p, p_w22p + W12N, HID, NSEG);
    pack_w2_kernel<<<(PREDL * 512 + 255)/256, 256>>>(Wtr, Wse, p_w2p, p_w2p + PREDL*512);
    // 4) seasonal MLP (bf16x3 tensor-core GEMMs, ldmatrix staging)
    bgemm_kernel<1,1><<<dim3(HID / 128, MMLP / 128), 256, SMEM_BYTES>>>(
        p_xsh, p_xsl, p_w11p, p_w11p + W11N, b11, nullptr, nullptr, p_hh, p_hl, MMLP, NSEG, HID);
    bgemm_kernel<0,1><<<dim3(1,         MMLP / 128), 256, SMEM_BYTES>>>(
        p_hh, p_hl, p_w12p, p_w12p + W12N, b12, nullptr, nullptr, p_xsh, p_xsl, MMLP, HID, NSEG);
    bgemm_kernel<1,1><<<dim3(HID / 128, MMLP / 128), 256, SMEM_BYTES>>>(
        p_xsh, p_xsl, p_w21p, p_w21p + W11N, b21, nullptr, nullptr, p_hh, p_hl, MMLP, NSEG, HID);
    bgemm_kernel<0,2><<<dim3(1,         MMLP / 128), 256, SMEM_BYTES>>>(
        p_hh, p_hl, p_w22p, p_w22p + W12N, b22, nullptr, nullptr, p_Abh, p_Abl, MMLP, HID, NSEG);
    // 5) fused heads: [trend|sea] @ [W_tr;W_se] (fp32 out)
    bgemm_kernel<0,0><<<dim3((PREDL + 127) / 128, BC / 128), 256, SMEM_BYTES>>>(
        p_Abh, p_Abl, p_w2p, p_w2p + PREDL*512, btr, bse, p_y, nullptr, nullptr, BC, 1024, PREDL);
    // 6) denorm + transpose
    final_kernel<<<dim3((PREDL + 31) / 32, (CH + 31) / 32, BATCH), dim3(32, 32)>>>(rw, rb, out);
}

// round 13
// speedup vs baseline: 3.1476x; 1.4651x over previous
#include <cuda_runtime.h>
#include <cuda_fp16.h>
#include <math.h>
#include <stdint.h>

#define BATCH 128
#define SEQL  512
#define CH    321
#define PREDL 336
#define KWIN  25
#define NSEG  128          // SEQL / 4
#define HID   512
#define BC    (BATCH*CH)   // 41088
#define MMLP  (BC*4)       // 164352

typedef __half fp16;

// ---------------- static scratch (no allocation allowed) ----------------
__device__ float g_mean[BC];
__device__ float g_std [BC];
__device__ fp16  g_A  [(size_t)BC*1024];        // [trend | sea-out], single fp16 plane
__device__ fp16  g_xs [(size_t)MMLP*NSEG];
__device__ fp16  g_h  [(size_t)MMLP*HID];
// weights packed N-MAJOR: [N][K/2] uint32 (fp16 k-pairs), hi plane then lo plane
__device__ uint32_t g_w11p[2][HID*(NSEG/2)];
__device__ uint32_t g_w12p[2][NSEG*(HID/2)];
__device__ uint32_t g_w21p[2][HID*(NSEG/2)];
__device__ uint32_t g_w22p[2][NSEG*(HID/2)];
__device__ uint32_t g_w2p [2][PREDL*512];       // concat [W_tr;W_se], K=1024
__device__ float g_y  [(size_t)BC*PREDL];

__device__ __forceinline__ void hsplit(float v, fp16& hi, fp16& lo) {
    hi = __float2half_rn(v);
    lo = __float2half_rn(v - __half2float(hi));
}
__device__ __forceinline__ uint32_t hpack(fp16 a, fp16 b) {
    return (uint32_t)__half_as_ushort(a) | ((uint32_t)__half_as_ushort(b) << 16);
}

// ---------------- fused: stats + normalize + decomp + interleave ----------------
#define NDC 16   // channels per block
__global__ __launch_bounds__(256)
void norm_decomp_kernel(const float* __restrict__ x,
                        const float* __restrict__ rw,
                        const float* __restrict__ rb) {
    __shared__ float sm[NDC][528];
    int b  = blockIdx.y;
    int c0 = blockIdx.x * NDC;
    int tid = threadIdx.x;
    // load RAW x (coalesced over channels)
    for (int idx = tid; idx < NDC * SEQL; idx += 256) {
        int ci = idx & (NDC - 1), l = idx >> 4;
        int c = c0 + ci;
        sm[ci][l] = (c < CH) ? x[((size_t)b * SEQL + l) * CH + c] : 0.f;
    }
    __syncthreads();
    int ci = tid >> 4;
    int lg = tid & 15;
    int c  = c0 + ci;
    // per-channel stats via 16-lane group reduction
    float s = 0.f, s2 = 0.f;
    #pragma unroll 4
    for (int i = 0; i < 32; ++i) {
        float v = sm[ci][lg + 16 * i];
        s += v; s2 += v * v;
    }
    #pragma unroll
    for (int k = 8; k; k >>= 1) {
        s  += __shfl_xor_sync(0xffffffffu, s,  k);
        s2 += __shfl_xor_sync(0xffffffffu, s2, k);
    }
    float m   = s * (1.0f / SEQL);
    float var = fmaxf(s2 * (1.0f / SEQL) - m * m, 0.f);
    float sd  = sqrtf(var + 1e-5f);
    if (c < CH) {
        float w = rw[c], bb = rb[c];
        float inv = w / sd;
        int row = b*CH + c;
        if (lg == 0) { g_mean[row] = m; g_std[row] = sd; }
        #pragma unroll 4
        for (int i = 0; i < 32; ++i) {
            int l = lg + 16 * i;
            float v = sm[ci][l];
            float ssum = 0.f;
            #pragma unroll
            for (int d = -12; d <= 12; ++d) {
                int j = l + d;
                j = j < 0 ? 0 : (j > SEQL - 1 ? SEQL - 1 : j);
                ssum += sm[ci][j];
            }
            float trend_r = ssum * (1.0f / KWIN);
            // MA commutes with the affine RevIN transform
            float trend_n = (trend_r - m) * inv + bb;
            float sea     = (v - trend_r) * inv;
            g_A[(size_t)row * 1024 + l] = __float2half_rn(trend_n);
            g_xs[((size_t)row * 4 + (l & 3)) * NSEG + (l >> 2)] = __float2half_rn(sea);
        }
    }
}

// ---------------- weight packing: [K][N] fp32 -> N-major [N][K/2] u32 fp16 pairs ----------------
__global__ void pack_w_kernel(const float* __restrict__ W,
                              uint32_t* __restrict__ Ph, uint32_t* __restrict__ Pl,
                              int Kd, int Nd) {
    int i = blockIdx.x * 256 + threadIdx.x;       // i = n*(Kd/2) + kp
    if (i >= Nd * (Kd / 2)) return;
    int n = i / (Kd / 2), kp = i - n * (Kd / 2);
    float v0 = W[(size_t)(2 * kp)     * Nd + n];
    float v1 = W[(size_t)(2 * kp + 1) * Nd + n];
    fp16 h0, l0, h1, l1;
    hsplit(v0, h0, l0);
    hsplit(v1, h1, l1);
    Ph[i] = hpack(h0, h1);
    Pl[i] = hpack(l0, l1);
}
__global__ void pack_w2_kernel(const float* __restrict__ Wtr,
                               const float* __restrict__ Wse,
                               uint32_t* __restrict__ Ph, uint32_t* __restrict__ Pl) {
    int i = blockIdx.x * 256 + threadIdx.x;       // i = n*512 + kp, K=1024
    if (i >= PREDL * 512) return;
    int n = i >> 9, kp = i & 511;
    int k0 = 2 * kp;
    const float* src = (k0 < 512) ? Wtr : Wse;
    int kb = (k0 < 512) ? 0 : 512;
    float v0 = src[(size_t)(k0 - kb)     * PREDL + n];
    float v1 = src[(size_t)(k0 - kb + 1) * PREDL + n];
    fp16 h0, l0, h1, l1;
    hsplit(v0, h0, l0);
    hsplit(v1, h1, l1);
    Ph[i] = hpack(h0, h1);
    Pl[i] = hpack(l0, l1);
}

// ======================= fp16x2 tensor-core GEMM (ldmatrix) =======================
// C = act(A@B + bias [+bias2]); A single fp16 plane, B fp16 (hi,lo) planes.
// Per k16: 2 MMA terms (a*bh + a*bl), fp32 accum; acc reuse distance 16.
__device__ __forceinline__ void mma16(float4& d, uint32_t a0, uint32_t a1,
                                      uint32_t a2, uint32_t a3,
                                      uint32_t b0, uint32_t b1) {
    asm volatile(
        "mma.sync.aligned.m16n8k16.row.col.f32.f16.f16.f32 "
        "{%0,%1,%2,%3},{%4,%5,%6,%7},{%8,%9},{%0,%1,%2,%3};"
        : "+f"(d.x), "+f"(d.y), "+f"(d.z), "+f"(d.w)
        : "r"(a0), "r"(a1), "r"(a2), "r"(a3), "r"(b0), "r"(b1));
}
__device__ __forceinline__ void cp16(uint32_t dst, const void* src, int bytes) {
    asm volatile("cp.async.cg.shared.global [%0], [%1], 16, %2;\n"
                 :: "r"(dst), "l"(src), "r"(bytes));
}
__device__ __forceinline__ void ldsm4(uint32_t& r0, uint32_t& r1, uint32_t& r2,
                                      uint32_t& r3, uint32_t addr) {
    asm volatile("ldmatrix.sync.aligned.m8n8.x4.shared.b16 {%0,%1,%2,%3}, [%4];"
                 : "=r"(r0), "=r"(r1), "=r"(r2), "=r"(r3) : "r"(addr));
}

#define BKT 32     // k-depth per tile (elements) = 16 kpair words
#define PA  20     // A smem row stride (words); conflict-free LDSM
#define PBK 20     // B smem row stride (words)
#define AS_WORDS (2*128*PA)                 // 5120  (single plane)
#define BS_WORDS (2*2*128*PBK)              // 10240 (2 planes)
#define SMEM_BYTES ((AS_WORDS+BS_WORDS)*4)  // 61440

// MODE: 0 = fp32 out; 1 = fp16 out; 2 = fp16 + interleave into head-A
template<int GELU, int MODE>
__global__ __launch_bounds__(256, 2)
void hgemm_kernel(const fp16* __restrict__ A_,
                  const uint32_t* __restrict__ Bhp, const uint32_t* __restrict__ Blp,
                  const float* __restrict__ bias, const float* __restrict__ bias2,
                  float* __restrict__ Cf, fp16* __restrict__ Ch,
                  int M, int Kd, int Nd) {
    extern __shared__ uint32_t smw[];
    uint32_t* Asw = smw;              // [2buf][128][PA]
    uint32_t* Bsw = smw + AS_WORDS;   // [2buf][2pl][128 n][PBK]

    const int tid  = threadIdx.x;
    const int lane = tid & 31, wid = tid >> 5;
    const int gid  = lane >> 2, tig = lane & 3;
    const int wm   = (wid & 1) * 64;
    const int wn   = (wid >> 1) * 32;
    const int m0   = blockIdx.y * 128;
    const int n0   = blockIdx.x * 128;
    const bool wactive = (n0 + wn) < Nd;

    const uint32_t As_base = (uint32_t)__cvta_generic_to_shared(Asw);
    const uint32_t Bs_base = (uint32_t)__cvta_generic_to_shared(Bsw);

    const int a_rowl = wm + (lane & 15);
    const int a_koff = (lane >> 4) * 4;
    const int b_rowl = wn + (lane & 7) + ((lane >> 4) << 3);
    const int b_koff = ((lane >> 3) & 1) * 4;

    float4 acc[4][4];
    #pragma unroll
    for (int i = 0; i < 4; ++i)
        #pragma unroll
        for (int j = 0; j < 4; ++j) acc[i][j] = make_float4(0.f, 0.f, 0.f, 0.f);

    auto fill = [&](int t, int buf) {
        const int k0 = t * BKT;
        // A: 128 rows x 4 chunks(16B = 8 fp16), single plane
        #pragma unroll
        for (int i = 0; i < 2; ++i) {
            int c = tid + 256 * i;
            int rr = (c >> 2) & 127, ch = c & 3;
            const fp16* src = A_ + (size_t)(m0 + rr) * Kd + k0 + ch * 8;
            uint32_t dst = As_base + (uint32_t)((((buf*128 + rr) * PA) + ch * 4) * 4);
            cp16(dst, src, 16);
        }
        // B (n-major): 2 planes x 128 n-rows x 4 chunks of 4 kpair-words
        #pragma unroll
        for (int i = 0; i < 4; ++i) {
            int c = tid + 256 * i;
            int pl = c >> 9, rr = (c >> 2) & 127, ch = c & 3;
            int n = n0 + rr;
            const uint32_t* base = pl ? Blp : Bhp;
            const uint32_t* src = base;
            int bytes = 0;
            if (n < Nd) { src = base + (size_t)n * (Kd/2) + k0/2 + ch * 4; bytes = 16; }
            uint32_t dst = Bs_base + (uint32_t)(((((buf*2+pl)*128 + rr) * PBK) + ch * 4) * 4);
            cp16(dst, src, bytes);
        }
    };

    fill(0, 0);
    asm volatile("cp.async.commit_group;");
    asm volatile("cp.async.wait_group 0;");
    __syncthreads();

    const int nk = Kd / BKT;
    for (int t = 0; t < nk; ++t) {
        const int buf = t & 1;
        if (t + 1 < nk) {
            fill(t + 1, buf ^ 1);
            asm volatile("cp.async.commit_group;");
        }
        if (wactive) {
            #pragma unroll
            for (int kk2 = 0; kk2 < 16; kk2 += 8) {
                const uint32_t aoff = As_base +
                    (uint32_t)((((buf*128 + a_rowl) * PA) + kk2 + a_koff) * 4);
                const uint32_t boff_hi = Bs_base +
                    (uint32_t)(((((buf*2+0)*128 + b_rowl) * PBK) + kk2 + b_koff) * 4);
                const uint32_t boff_lo = boff_hi + (uint32_t)(128 * PBK * 4);

                uint32_t bh[4][2], bl[4][2], af[4][4];
                ldsm4(bh[0][0], bh[0][1], bh[1][0], bh[1][1], boff_hi);
                ldsm4(bh[2][0], bh[2][1], bh[3][0], bh[3][1], boff_hi + 16*PBK*4);
                ldsm4(bl[0][0], bl[0][1], bl[1][0], bl[1][1], boff_lo);
                ldsm4(bl[2][0], bl[2][1], bl[3][0], bl[3][1], boff_lo + 16*PBK*4);
                #pragma unroll
                for (int mt = 0; mt < 4; ++mt)
                    ldsm4(af[mt][0], af[mt][1], af[mt][2], af[mt][3],
                          aoff + mt * 16*PA*4);
                // term 0: a * bh  (acc reuse distance 16)
                #pragma unroll
                for (int mt = 0; mt < 4; ++mt)
                    #pragma unroll
                    for (int nt = 0; nt < 4; ++nt)
                        mma16(acc[mt][nt], af[mt][0], af[mt][1], af[mt][2], af[mt][3],
                              bh[nt][0], bh[nt][1]);
                // term 1: a * bl
                #pragma unroll
                for (int mt = 0; mt < 4; ++mt)
                    #pragma unroll
                    for (int nt = 0; nt < 4; ++nt)
                        mma16(acc[mt][nt], af[mt][0], af[mt][1], af[mt][2], af[mt][3],
                              bl[nt][0], bl[nt][1]);
            }
        }
        if (t + 1 < nk) asm volatile("cp.async.wait_group 0;");
        __syncthreads();
    }

    // epilogue (paired stores; col even, Nd even)
    auto emit2 = [&](int row, int col, float v0, float v1) {
        if (col >= Nd) return;
        v0 += bias[col]; v1 += bias[col + 1];
        if (bias2) { v0 += bias2[col]; v1 += bias2[col + 1]; }
        if (GELU) {
            v0 = 0.5f * v0 * (1.0f + erff(v0 * 0.70710678118654752f));
            v1 = 0.5f * v1 * (1.0f + erff(v1 * 0.70710678118654752f));
        }
        if (MODE == 0) {
            *reinterpret_cast<float2*>(&Cf[(size_t)row * Nd + col]) = make_float2(v0, v1);
        } else if (MODE == 1) {
            *reinterpret_cast<uint32_t*>(&Ch[(size_t)row * Nd + col]) =
                hpack(__float2half_rn(v0), __float2half_rn(v1));
        } else {
            size_t i0 = ((size_t)(row >> 2)) * 1024 + 512 + (size_t)col * 4 + (row & 3);
            Ch[i0]     = __float2half_rn(v0);
            Ch[i0 + 4] = __float2half_rn(v1);
        }
    };
    #pragma unroll
    for (int mt = 0; mt < 4; ++mt) {
        int r0 = m0 + wm + mt * 16 + gid;
        #pragma unroll
        for (int nt = 0; nt < 4; ++nt) {
            int c0 = n0 + wn + nt * 8 + 2 * tig;
            float4 c = acc[mt][nt];
            emit2(r0,     c0, c.x, c.y);
            emit2(r0 + 8, c0, c.z, c.w);
        }
    }
}

// ---------------- final: denorm + transpose to [B, PRED, C] ----------------
__global__ void final_kernel(const float* __restrict__ rw,
                             const float* __restrict__ rb,
                             float* __restrict__ out) {
    __shared__ float sm[32][33];
    int b  = blockIdx.z;
    int p0 = blockIdx.x * 32, c0 = blockIdx.y * 32;
    int tx = threadIdx.x, ty = threadIdx.y;
    int p = p0 + tx, c = c0 + ty;
    if (p < PREDL && c < CH)
        sm[ty][tx] = g_y[((size_t)(b*CH + c)) * PREDL + p];
    __syncthreads();
    int cw = c0 + tx, pw = p0 + ty;
    if (cw < CH && pw < PREDL) {
        float v = sm[tx][ty];
        v = (v - rb[cw]) / (rw[cw] + 1e-10f);
        v = v * g_std[b*CH + cw] + g_mean[b*CH + cw];
        out[((size_t)b * PREDL + pw) * CH + cw] = v;
    }
}

// ---------------- launch ----------------
extern "C" void kernel_launch(void* const* d_in, const int* in_sizes, int n_in,
                              void* d_out, int out_size) {
    const float* x   = (const float*)d_in[0];
    const float* rw  = (const float*)d_in[1];
    const float* rb  = (const float*)d_in[2];
    const float* W11 = (const float*)d_in[3];
    const float* b11 = (const float*)d_in[4];
    const float* W12 = (const float*)d_in[5];
    const float* b12 = (const float*)d_in[6];
    const float* W21 = (const float*)d_in[7];
    const float* b21 = (const float*)d_in[8];
    const float* W22 = (const float*)d_in[9];
    const float* b22 = (const float*)d_in[10];
    const float* Wtr = (const float*)d_in[11];
    const float* btr = (const float*)d_in[12];
    const float* Wse = (const float*)d_in[13];
    const float* bse = (const float*)d_in[14];
    float* out = (float*)d_out;
    (void)in_sizes; (void)n_in; (void)out_size;

    fp16 *p_A, *p_xs, *p_h;
    uint32_t *p_w11p, *p_w12p, *p_w21p, *p_w22p, *p_w2p;
    float *p_y;
    cudaGetSymbolAddress((void**)&p_A,  g_A);
    cudaGetSymbolAddress((void**)&p_xs, g_xs);
    cudaGetSymbolAddress((void**)&p_h,  g_h);
    cudaGetSymbolAddress((void**)&p_w11p, g_w11p);
    cudaGetSymbolAddress((void**)&p_w12p, g_w12p);
    cudaGetSymbolAddress((void**)&p_w21p, g_w21p);
    cudaGetSymbolAddress((void**)&p_w22p, g_w22p);
    cudaGetSymbolAddress((void**)&p_w2p,  g_w2p);
    cudaGetSymbolAddress((void**)&p_y,    g_y);

    cudaFuncSetAttribute(hgemm_kernel<1,1>, cudaFuncAttributeMaxDynamicSharedMemorySize, SMEM_BYTES);
    cudaFuncSetAttribute(hgemm_kernel<0,1>, cudaFuncAttributeMaxDynamicSharedMemorySize, SMEM_BYTES);
    cudaFuncSetAttribute(hgemm_kernel<0,2>, cudaFuncAttributeMaxDynamicSharedMemorySize, SMEM_BYTES);
    cudaFuncSetAttribute(hgemm_kernel<0,0>, cudaFuncAttributeMaxDynamicSharedMemorySize, SMEM_BYTES);

    const int W11N = HID*(NSEG/2), W12N = NSEG*(HID/2);

    // 0) pack weights (independent of activations, launch first)
    pack_w_kernel<<<(W11N + 255)/256, 256>>>(W11, p_w11p, p_w11p + W11N, NSEG, HID);
    pack_w_kernel<<<(W12N + 255)/256, 256>>>(W12, p_w12p, p_w12p + W12N, HID, NSEG);
    pack_w_kernel<<<(W11N + 255)/256, 256>>>(W21, p_w21p, p_w21p + W11N, NSEG, HID);
    pack_w_kernel<<<(W12N + 255)/256, 256>>>(W22, p_w22p, p_w22p + W12N, HID, NSEG);
    pack_w2_kernel<<<(PREDL * 512 + 255)/256, 256>>>(Wtr, Wse, p_w2p, p_w2p + PREDL*512);
    // 1) fused stats + normalize + decomposition (+ fp16, interleave)
    norm_decomp_kernel<<<dim3((CH + NDC - 1) / NDC, BATCH), 256>>>(x, rw, rb);
    // 2) seasonal MLP (fp16x2 tensor-core GEMMs)
    hgemm_kernel<1,1><<<dim3(HID / 128, MMLP / 128), 256, SMEM_BYTES>>>(
        p_xs, p_w11p, p_w11p + W11N, b11, nullptr, nullptr, p_h, MMLP, NSEG, HID);
    hgemm_kernel<0,1><<<dim3(1,         MMLP / 128), 256, SMEM_BYTES>>>(
        p_h, p_w12p, p_w12p + W12N, b12, nullptr, nullptr, p_xs, MMLP, HID, NSEG);
    hgemm_kernel<1,1><<<dim3(HID / 128, MMLP / 128), 256, SMEM_BYTES>>>(
        p_xs, p_w21p, p_w21p + W11N, b21, nullptr, nullptr, p_h, MMLP, NSEG, HID);
    hgemm_kernel<0,2><<<dim3(1,         MMLP / 128), 256, SMEM_BYTES>>>(
        p_h, p_w22p, p_w22p + W12N, b22, nullptr, nullptr, p_A, MMLP, HID, NSEG);
    // 3) fused heads: [trend|sea] @ [W_tr;W_se] (fp32 out)
    hgemm_kernel<0,0><<<dim3((PREDL + 127) / 128, BC / 128), 256, SMEM_BYTES>>>(
        p_A, p_w2p, p_w2p + PREDL*512, btr, bse, p_y, nullptr, BC, 1024, PREDL);
    // 4) denorm + transpose
    final_kernel<<<dim3((PREDL + 31) / 32, (CH + 31) / 32, BATCH), dim3(32, 32)>>>(rw, rb, out);
}

// round 15
// speedup vs baseline: 3.9099x; 1.2422x over previous
#include <cuda_runtime.h>
#include <cuda_fp16.h>
#include <math.h>
#include <stdint.h>

#define BATCH 128
#define SEQL  512
#define CH    321
#define PREDL 336
#define KWIN  25
#define NSEG  128          // SEQL / 4
#define HID   512
#define BC    (BATCH*CH)   // 41088
#define MMLP  (BC*4)       // 164352

typedef __half fp16;

// ---------------- static scratch (no allocation allowed) ----------------
__device__ float g_mean[BC];
__device__ float g_std [BC];
__device__ fp16  g_A  [(size_t)BC*1024];        // [trend | sea-out], fp16
__device__ fp16  g_xs [(size_t)MMLP*NSEG];
__device__ fp16  g_h  [(size_t)MMLP*HID];
// weights packed N-MAJOR: [N][K/2] uint32 (fp16 k-pairs), single plane
__device__ uint32_t g_w11p[HID*(NSEG/2)];
__device__ uint32_t g_w12p[NSEG*(HID/2)];
__device__ uint32_t g_w21p[HID*(NSEG/2)];
__device__ uint32_t g_w22p[NSEG*(HID/2)];
__device__ uint32_t g_w2p [PREDL*512];          // concat [W_tr;W_se], K=1024
__device__ float g_y  [(size_t)BC*PREDL];

__device__ __forceinline__ uint32_t hpack(fp16 a, fp16 b) {
    return (uint32_t)__half_as_ushort(a) | ((uint32_t)__half_as_ushort(b) << 16);
}

// ---------------- fused: stats + normalize + decomp + interleave ----------------
#define NDC 16   // channels per block
__global__ __launch_bounds__(256)
void norm_decomp_kernel(const float* __restrict__ x,
                        const float* __restrict__ rw,
                        const float* __restrict__ rb) {
    __shared__ float sm[NDC][528];
    int b  = blockIdx.y;
    int c0 = blockIdx.x * NDC;
    int tid = threadIdx.x;
    for (int idx = tid; idx < NDC * SEQL; idx += 256) {
        int ci = idx & (NDC - 1), l = idx >> 4;
        int c = c0 + ci;
        sm[ci][l] = (c < CH) ? x[((size_t)b * SEQL + l) * CH + c] : 0.f;
    }
    __syncthreads();
    int ci = tid >> 4;
    int lg = tid & 15;
    int c  = c0 + ci;
    float s = 0.f, s2 = 0.f;
    #pragma unroll 4
    for (int i = 0; i < 32; ++i) {
        float v = sm[ci][lg + 16 * i];
        s += v; s2 += v * v;
    }
    #pragma unroll
    for (int k = 8; k; k >>= 1) {
        s  += __shfl_xor_sync(0xffffffffu, s,  k);
        s2 += __shfl_xor_sync(0xffffffffu, s2, k);
    }
    float m   = s * (1.0f / SEQL);
    float var = fmaxf(s2 * (1.0f / SEQL) - m * m, 0.f);
    float sd  = sqrtf(var + 1e-5f);
    if (c < CH) {
        float w = rw[c], bb = rb[c];
        float inv = w / sd;
        int row = b*CH + c;
        if (lg == 0) { g_mean[row] = m; g_std[row] = sd; }
        #pragma unroll 4
        for (int i = 0; i < 32; ++i) {
            int l = lg + 16 * i;
            float v = sm[ci][l];
            float ssum = 0.f;
            #pragma unroll
            for (int d = -12; d <= 12; ++d) {
                int j = l + d;
                j = j < 0 ? 0 : (j > SEQL - 1 ? SEQL - 1 : j);
                ssum += sm[ci][j];
            }
            float trend_r = ssum * (1.0f / KWIN);
            float trend_n = (trend_r - m) * inv + bb;   // MA commutes with affine RevIN
            float sea     = (v - trend_r) * inv;
            g_A[(size_t)row * 1024 + l] = __float2half_rn(trend_n);
            g_xs[((size_t)row * 4 + (l & 3)) * NSEG + (l >> 2)] = __float2half_rn(sea);
        }
    }
}

// ---------------- weight packing: [K][N] fp32 -> N-major [N][K/2] u32 fp16 pairs ----------------
__global__ void pack_w_kernel(const float* __restrict__ W,
                              uint32_t* __restrict__ P, int Kd, int Nd) {
    int i = blockIdx.x * 256 + threadIdx.x;       // i = n*(Kd/2) + kp
    if (i >= Nd * (Kd / 2)) return;
    int n = i / (Kd / 2), kp = i - n * (Kd / 2);
    float v0 = W[(size_t)(2 * kp)     * Nd + n];
    float v1 = W[(size_t)(2 * kp + 1) * Nd + n];
    P[i] = hpack(__float2half_rn(v0), __float2half_rn(v1));
}
__global__ void pack_w2_kernel(const float* __restrict__ Wtr,
                               const float* __restrict__ Wse,
                               uint32_t* __restrict__ P) {
    int i = blockIdx.x * 256 + threadIdx.x;       // i = n*512 + kp, K=1024
    if (i >= PREDL * 512) return;
    int n = i >> 9, kp = i & 511;
    int k0 = 2 * kp;
    const float* src = (k0 < 512) ? Wtr : Wse;
    int kb = (k0 < 512) ? 0 : 512;
    float v0 = src[(size_t)(k0 - kb)     * PREDL + n];
    float v1 = src[(size_t)(k0 - kb + 1) * PREDL + n];
    P[i] = hpack(__float2half_rn(v0), __float2half_rn(v1));
}

// ======================= fp16 tensor-core GEMM (ldmatrix) =======================
// C = act(A@B + bias [+bias2]); A, B single fp16 planes, fp32 accum.
__device__ __forceinline__ void mma16(float4& d, uint32_t a0, uint32_t a1,
                                      uint32_t a2, uint32_t a3,
                                      uint32_t b0, uint32_t b1) {
    asm volatile(
        "mma.sync.aligned.m16n8k16.row.col.f32.f16.f16.f32 "
        "{%0,%1,%2,%3},{%4,%5,%6,%7},{%8,%9},{%0,%1,%2,%3};"
        : "+f"(d.x), "+f"(d.y), "+f"(d.z), "+f"(d.w)
        : "r"(a0), "r"(a1), "r"(a2), "r"(a3), "r"(b0), "r"(b1));
}
__device__ __forceinline__ void cp16(uint32_t dst, const void* src, int bytes) {
    asm volatile("cp.async.cg.shared.global [%0], [%1], 16, %2;\n"
                 :: "r"(dst), "l"(src), "r"(bytes));
}
__device__ __forceinline__ void ldsm4(uint32_t& r0, uint32_t& r1, uint32_t& r2,
                                      uint32_t& r3, uint32_t addr) {
    asm volatile("ldmatrix.sync.aligned.m8n8.x4.shared.b16 {%0,%1,%2,%3}, [%4];"
                 : "=r"(r0), "=r"(r1), "=r"(r2), "=r"(r3) : "r"(addr));
}

#define BKT 32     // k-depth per tile (elements) = 16 kpair words
#define PA  20     // A smem row stride (words); conflict-free LDSM
#define PBK 20     // B smem row stride (words)
#define AS_WORDS (2*128*PA)                 // 5120
#define BS_WORDS (2*128*PBK)                // 5120
#define SMEM_BYTES ((AS_WORDS+BS_WORDS)*4)  // 40960

// MODE: 0 = fp32 out; 1 = fp16 out; 2 = fp16 + interleave into head-A
template<int GELU, int MODE>
__global__ __launch_bounds__(256, 2)
void hgemm_kernel(const fp16* __restrict__ A_,
                  const uint32_t* __restrict__ Bp,
                  const float* __restrict__ bias, const float* __restrict__ bias2,
                  float* __restrict__ Cf, fp16* __restrict__ Ch,
                  int M, int Kd, int Nd) {
    extern __shared__ uint32_t smw[];
    uint32_t* Asw = smw;              // [2buf][128][PA]
    uint32_t* Bsw = smw + AS_WORDS;   // [2buf][128 n][PBK]

    const int tid  = threadIdx.x;
    const int lane = tid & 31, wid = tid >> 5;
    const int gid  = lane >> 2, tig = lane & 3;
    const int wm   = (wid & 1) * 64;
    const int wn   = (wid >> 1) * 32;
    const int m0   = blockIdx.y * 128;
    const int n0   = blockIdx.x * 128;
    const bool wactive = (n0 + wn) < Nd;

    const uint32_t As_base = (uint32_t)__cvta_generic_to_shared(Asw);
    const uint32_t Bs_base = (uint32_t)__cvta_generic_to_shared(Bsw);

    const int a_rowl = wm + (lane & 15);
    const int a_koff = (lane >> 4) * 4;
    const int b_rowl = wn + (lane & 7) + ((lane >> 4) << 3);
    const int b_koff = ((lane >> 3) & 1) * 4;

    float4 acc[4][4];
    #pragma unroll
    for (int i = 0; i < 4; ++i)
        #pragma unroll
        for (int j = 0; j < 4; ++j) acc[i][j] = make_float4(0.f, 0.f, 0.f, 0.f);

    auto fill = [&](int t, int buf) {
        const int k0 = t * BKT;
        // A: 128 rows x 4 chunks(16B = 8 fp16)
        #pragma unroll
        for (int i = 0; i < 2; ++i) {
            int c = tid + 256 * i;
            int rr = (c >> 2) & 127, ch = c & 3;
            const fp16* src = A_ + (size_t)(m0 + rr) * Kd + k0 + ch * 8;
            uint32_t dst = As_base + (uint32_t)((((buf*128 + rr) * PA) + ch * 4) * 4);
            cp16(dst, src, 16);
        }
        // B (n-major): 128 n-rows x 4 chunks of 4 kpair-words
        #pragma unroll
        for (int i = 0; i < 2; ++i) {
            int c = tid + 256 * i;
            int rr = (c >> 2) & 127, ch = c & 3;
            int n = n0 + rr;
            const uint32_t* src = Bp;
            int bytes = 0;
            if (n < Nd) { src = Bp + (size_t)n * (Kd/2) + k0/2 + ch * 4; bytes = 16; }
            uint32_t dst = Bs_base + (uint32_t)((((buf*128 + rr) * PBK) + ch * 4) * 4);
            cp16(dst, src, bytes);
        }
    };

    fill(0, 0);
    asm volatile("cp.async.commit_group;");
    asm volatile("cp.async.wait_group 0;");
    __syncthreads();

    const int nk = Kd / BKT;
    for (int t = 0; t < nk; ++t) {
        const int buf = t & 1;
        if (t + 1 < nk) {
            fill(t + 1, buf ^ 1);
            asm volatile("cp.async.commit_group;");
        }
        if (wactive) {
            #pragma unroll
            for (int kk2 = 0; kk2 < 16; kk2 += 8) {
                const uint32_t aoff = As_base +
                    (uint32_t)((((buf*128 + a_rowl) * PA) + kk2 + a_koff) * 4);
                const uint32_t boff = Bs_base +
                    (uint32_t)((((buf*128 + b_rowl) * PBK) + kk2 + b_koff) * 4);

                uint32_t bh[4][2], af[4][4];
                ldsm4(bh[0][0], bh[0][1], bh[1][0], bh[1][1], boff);
                ldsm4(bh[2][0], bh[2][1], bh[3][0], bh[3][1], boff + 16*PBK*4);
                #pragma unroll
                for (int mt = 0; mt < 4; ++mt)
                    ldsm4(af[mt][0], af[mt][1], af[mt][2], af[mt][3],
                          aoff + mt * 16*PA*4);
                #pragma unroll
                for (int mt = 0; mt < 4; ++mt)
                    #pragma unroll
                    for (int nt = 0; nt < 4; ++nt)
                        mma16(acc[mt][nt], af[mt][0], af[mt][1], af[mt][2], af[mt][3],
                              bh[nt][0], bh[nt][1]);
            }
        }
        if (t + 1 < nk) asm volatile("cp.async.wait_group 0;");
        __syncthreads();
    }

    // epilogue (paired stores; col even, Nd even)
    auto emit2 = [&](int row, int col, float v0, float v1) {
        if (col >= Nd) return;
        v0 += bias[col]; v1 += bias[col + 1];
        if (bias2) { v0 += bias2[col]; v1 += bias2[col + 1]; }
        if (GELU) {
            v0 = 0.5f * v0 * (1.0f + erff(v0 * 0.70710678118654752f));
            v1 = 0.5f * v1 * (1.0f + erff(v1 * 0.70710678118654752f));
        }
        if (MODE == 0) {
            *reinterpret_cast<float2*>(&Cf[(size_t)row * Nd + col]) = make_float2(v0, v1);
        } else if (MODE == 1) {
            *reinterpret_cast<uint32_t*>(&Ch[(size_t)row * Nd + col]) =
                hpack(__float2half_rn(v0), __float2half_rn(v1));
        } else {
            size_t i0 = ((size_t)(row >> 2)) * 1024 + 512 + (size_t)col * 4 + (row & 3);
            Ch[i0]     = __float2half_rn(v0);
            Ch[i0 + 4] = __float2half_rn(v1);
        }
    };
    #pragma unroll
    for (int mt = 0; mt < 4; ++mt) {
        int r0 = m0 + wm + mt * 16 + gid;
        #pragma unroll
        for (int nt = 0; nt < 4; ++nt) {
            int c0 = n0 + wn + nt * 8 + 2 * tig;
            float4 c = acc[mt][nt];
            emit2(r0,     c0, c.x, c.y);
            emit2(r0 + 8, c0, c.z, c.w);
        }
    }
}

// ---------------- final: denorm + transpose to [B, PRED, C] ----------------
__global__ void final_kernel(const float* __restrict__ rw,
                             const float* __restrict__ rb,
                             float* __restrict__ out) {
    __shared__ float sm[32][33];
    int b  = blockIdx.z;
    int p0 = blockIdx.x * 32, c0 = blockIdx.y * 32;
    int tx = threadIdx.x, ty = threadIdx.y;
    int p = p0 + tx, c = c0 + ty;
    if (p < PREDL && c < CH)
        sm[ty][tx] = g_y[((size_t)(b*CH + c)) * PREDL + p];
    __syncthreads();
    int cw = c0 + tx, pw = p0 + ty;
    if (cw < CH && pw < PREDL) {
        float v = sm[tx][ty];
        v = (v - rb[cw]) / (rw[cw] + 1e-10f);
        v = v * g_std[b*CH + cw] + g_mean[b*CH + cw];
        out[((size_t)b * PREDL + pw) * CH + cw] = v;
    }
}

// ---------------- launch ----------------
extern "C" void kernel_launch(void* const* d_in, const int* in_sizes, int n_in,
                              void* d_out, int out_size) {
    const float* x   = (const float*)d_in[0];
    const float* rw  = (const float*)d_in[1];
    const float* rb  = (const float*)d_in[2];
    const float* W11 = (const float*)d_in[3];
    const float* b11 = (const float*)d_in[4];
    const float* W12 = (const float*)d_in[5];
    const float* b12 = (const float*)d_in[6];
    const float* W21 = (const float*)d_in[7];
    const float* b21 = (const float*)d_in[8];
    const float* W22 = (const float*)d_in[9];
    const float* b22 = (const float*)d_in[10];
    const float* Wtr = (const float*)d_in[11];
    const float* btr = (const float*)d_in[12];
    const float* Wse = (const float*)d_in[13];
    const float* bse = (const float*)d_in[14];
    float* out = (float*)d_out;
    (void)in_sizes; (void)n_in; (void)out_size;

    fp16 *p_A, *p_xs, *p_h;
    uint32_t *p_w11p, *p_w12p, *p_w21p, *p_w22p, *p_w2p;
    float *p_y;
    cudaGetSymbolAddress((void**)&p_A,  g_A);
    cudaGetSymbolAddress((void**)&p_xs, g_xs);
    cudaGetSymbolAddress((void**)&p_h,  g_h);
    cudaGetSymbolAddress((void**)&p_w11p, g_w11p);
    cudaGetSymbolAddress((void**)&p_w12p, g_w12p);
    cudaGetSymbolAddress((void**)&p_w21p, g_w21p);
    cudaGetSymbolAddress((void**)&p_w22p, g_w22p);
    cudaGetSymbolAddress((void**)&p_w2p,  g_w2p);
    cudaGetSymbolAddress((void**)&p_y,    g_y);

    cudaFuncSetAttribute(hgemm_kernel<1,1>, cudaFuncAttributeMaxDynamicSharedMemorySize, SMEM_BYTES);
    cudaFuncSetAttribute(hgemm_kernel<0,1>, cudaFuncAttributeMaxDynamicSharedMemorySize, SMEM_BYTES);
    cudaFuncSetAttribute(hgemm_kernel<0,2>, cudaFuncAttributeMaxDynamicSharedMemorySize, SMEM_BYTES);
    cudaFuncSetAttribute(hgemm_kernel<0,0>, cudaFuncAttributeMaxDynamicSharedMemorySize, SMEM_BYTES);

    const int W11N = HID*(NSEG/2), W12N = NSEG*(HID/2);

    // 0) pack weights (independent of activations)
    pack_w_kernel<<<(W11N + 255)/256, 256>>>(W11, p_w11p, NSEG, HID);
    pack_w_kernel<<<(W12N + 255)/256, 256>>>(W12, p_w12p, HID, NSEG);
    pack_w_kernel<<<(W11N + 255)/256, 256>>>(W21, p_w21p, NSEG, HID);
    pack_w_kernel<<<(W12N + 255)/256, 256>>>(W22, p_w22p, HID, NSEG);
    pack_w2_kernel<<<(PREDL * 512 + 255)/256, 256>>>(Wtr, Wse, p_w2p);
    // 1) fused stats + normalize + decomposition (+ fp16, interleave)
    norm_decomp_kernel<<<dim3((CH + NDC - 1) / NDC, BATCH), 256>>>(x, rw, rb);
    // 2) seasonal MLP (fp16 tensor-core GEMMs)
    hgemm_kernel<1,1><<<dim3(HID / 128, MMLP / 128), 256, SMEM_BYTES>>>(
        p_xs, p_w11p, b11, nullptr, nullptr, p_h, MMLP, NSEG, HID);
    hgemm_kernel<0,1><<<dim3(1,         MMLP / 128), 256, SMEM_BYTES>>>(
        p_h, p_w12p, b12, nullptr, nullptr, p_xs, MMLP, HID, NSEG);
    hgemm_kernel<1,1><<<dim3(HID / 128, MMLP / 128), 256, SMEM_BYTES>>>(
        p_xs, p_w21p, b21, nullptr, nullptr, p_h, MMLP, NSEG, HID);
    hgemm_kernel<0,2><<<dim3(1,         MMLP / 128), 256, SMEM_BYTES>>>(
        p_h, p_w22p, b22, nullptr, nullptr, p_A, MMLP, HID, NSEG);
    // 3) fused heads: [trend|sea] @ [W_tr;W_se] (fp32 out)
    hgemm_kernel<0,0><<<dim3((PREDL + 127) / 128, BC / 128), 256, SMEM_BYTES>>>(
        p_A, p_w2p, btr, bse, p_y, nullptr, BC, 1024, PREDL);
    // 4) denorm + transpose
    final_kernel<<<dim3((PREDL + 31) / 32, (CH + 31) / 32, BATCH), dim3(32, 32)>>>(rw, rb, out);
}

// round 17
// speedup vs baseline: 4.0563x; 1.0374x over previous
#include <cuda_runtime.h>
#include <cuda_fp16.h>
#include <math.h>
#include <stdint.h>

#define BATCH 128
#define SEQL  512
#define CH    321
#define PREDL 336
#define KWIN  25
#define NSEG  128          // SEQL / 4
#define HID   512
#define BC    (BATCH*CH)   // 41088
#define MMLP  (BC*4)       // 164352

typedef __half fp16;

// ---------------- static scratch (no allocation allowed) ----------------
__device__ float g_mean[BC];
__device__ float g_std [BC];
__device__ fp16  g_A  [(size_t)BC*1024];        // [trend | sea-out(perm)], fp16
__device__ fp16  g_xs [(size_t)MMLP*NSEG];
__device__ fp16  g_h  [(size_t)MMLP*HID];
// weights packed N-MAJOR: [N][K/2] uint32 (fp16 k-pairs)
__device__ uint32_t g_w11p[HID*(NSEG/2)];
__device__ uint32_t g_w12p[NSEG*(HID/2)];
__device__ uint32_t g_w21p[HID*(NSEG/2)];
__device__ uint32_t g_w22p[NSEG*(HID/2)];
__device__ uint32_t g_w2p [PREDL*512];          // concat [W_tr;W_se(perm)], K=1024
__device__ float g_y  [(size_t)BC*PREDL];

__device__ __forceinline__ uint32_t hpack(fp16 a, fp16 b) {
    return (uint32_t)__half_as_ushort(a) | ((uint32_t)__half_as_ushort(b) << 16);
}

// ---------------- fused: stats + normalize + decomp + interleave ----------------
#define NDC 16   // channels per block
__global__ __launch_bounds__(256)
void norm_decomp_kernel(const float* __restrict__ x,
                        const float* __restrict__ rw,
                        const float* __restrict__ rb) {
    __shared__ float sm[NDC][528];
    int b  = blockIdx.y;
    int c0 = blockIdx.x * NDC;
    int tid = threadIdx.x;
    for (int idx = tid; idx < NDC * SEQL; idx += 256) {
        int ci = idx & (NDC - 1), l = idx >> 4;
        int c = c0 + ci;
        sm[ci][l] = (c < CH) ? x[((size_t)b * SEQL + l) * CH + c] : 0.f;
    }
    __syncthreads();
    int ci = tid >> 4;
    int lg = tid & 15;
    int c  = c0 + ci;
    float s = 0.f, s2 = 0.f;
    #pragma unroll 4
    for (int i = 0; i < 32; ++i) {
        float v = sm[ci][lg + 16 * i];
        s += v; s2 += v * v;
    }
    #pragma unroll
    for (int k = 8; k; k >>= 1) {
        s  += __shfl_xor_sync(0xffffffffu, s,  k);
        s2 += __shfl_xor_sync(0xffffffffu, s2, k);
    }
    float m   = s * (1.0f / SEQL);
    float var = fmaxf(s2 * (1.0f / SEQL) - m * m, 0.f);
    float sd  = sqrtf(var + 1e-5f);
    if (c < CH) {
        float w = rw[c], bb = rb[c];
        float inv = w / sd;
        int row = b*CH + c;
        if (lg == 0) { g_mean[row] = m; g_std[row] = sd; }
        #pragma unroll 4
        for (int i = 0; i < 32; ++i) {
            int l = lg + 16 * i;
            float v = sm[ci][l];
            float ssum = 0.f;
            #pragma unroll
            for (int d = -12; d <= 12; ++d) {
                int j = l + d;
                j = j < 0 ? 0 : (j > SEQL - 1 ? SEQL - 1 : j);
                ssum += sm[ci][j];
            }
            float trend_r = ssum * (1.0f / KWIN);
            float trend_n = (trend_r - m) * inv + bb;   // MA commutes with affine RevIN
            float sea     = (v - trend_r) * inv;
            g_A[(size_t)row * 1024 + l] = __float2half_rn(trend_n);
            g_xs[((size_t)row * 4 + (l & 3)) * NSEG + (l >> 2)] = __float2half_rn(sea);
        }
    }
}

// ---------------- fused weight packing (single launch) ----------------
// Standard: [K][N] fp32 -> N-major [N][K/2] u32 fp16 pairs.
// Head W2: [W_tr ; W_se] with W_se rows PERMUTED (l = (m&127)*4 + m>>7) so that
// GEMM4's natural row-major output order is the head's K ordering.
#define SEG1 (HID*(NSEG/2))
#define SEG2 (SEG1 + NSEG*(HID/2))
#define SEG3 (SEG2 + HID*(NSEG/2))
#define SEG4 (SEG3 + NSEG*(HID/2))
#define SEG5 (SEG4 + PREDL*512)
__global__ void pack_all_kernel(const float* __restrict__ W11, const float* __restrict__ W12,
                                const float* __restrict__ W21, const float* __restrict__ W22,
                                const float* __restrict__ Wtr, const float* __restrict__ Wse) {
    int i = blockIdx.x * 256 + threadIdx.x;
    if (i >= SEG5) return;
    if (i < SEG4) {
        const float* W; uint32_t* P; int Kd, Nd, j;
        if (i < SEG1)      { W = W11; P = g_w11p; Kd = NSEG; Nd = HID;  j = i; }
        else if (i < SEG2) { W = W12; P = g_w12p; Kd = HID;  Nd = NSEG; j = i - SEG1; }
        else if (i < SEG3) { W = W21; P = g_w21p; Kd = NSEG; Nd = HID;  j = i - SEG2; }
        else               { W = W22; P = g_w22p; Kd = HID;  Nd = NSEG; j = i - SEG3; }
        int n = j / (Kd / 2), kp = j - n * (Kd / 2);
        float v0 = W[(size_t)(2 * kp)     * Nd + n];
        float v1 = W[(size_t)(2 * kp + 1) * Nd + n];
        P[j] = hpack(__float2half_rn(v0), __float2half_rn(v1));
    } else {
        int j = i - SEG4;                 // j = p*512 + kp, K=1024
        int p = j >> 9, kp = j & 511;
        auto wval = [&](int k) -> float {
            if (k < 512) return Wtr[(size_t)k * PREDL + p];
            int m = k - 512;
            int l = (m & 127) * 4 + (m >> 7);   // inverse interleave permutation
            return Wse[(size_t)l * PREDL + p];
        };
        g_w2p[j] = hpack(__float2half_rn(wval(2 * kp)), __float2half_rn(wval(2 * kp + 1)));
    }
}

// ======================= fp16 tensor-core GEMM (ldmatrix, 3-stage) ===============
__device__ __forceinline__ void mma16(float4& d, uint32_t a0, uint32_t a1,
                                      uint32_t a2, uint32_t a3,
                                      uint32_t b0, uint32_t b1) {
    asm volatile(
        "mma.sync.aligned.m16n8k16.row.col.f32.f16.f16.f32 "
        "{%0,%1,%2,%3},{%4,%5,%6,%7},{%8,%9},{%0,%1,%2,%3};"
        : "+f"(d.x), "+f"(d.y), "+f"(d.z), "+f"(d.w)
        : "r"(a0), "r"(a1), "r"(a2), "r"(a3), "r"(b0), "r"(b1));
}
__device__ __forceinline__ void cp16(uint32_t dst, const void* src, int bytes) {
    asm volatile("cp.async.cg.shared.global [%0], [%1], 16, %2;\n"
                 :: "r"(dst), "l"(src), "r"(bytes));
}
__device__ __forceinline__ void ldsm4(uint32_t& r0, uint32_t& r1, uint32_t& r2,
                                      uint32_t& r3, uint32_t addr) {
    asm volatile("ldmatrix.sync.aligned.m8n8.x4.shared.b16 {%0,%1,%2,%3}, [%4];"
                 : "=r"(r0), "=r"(r1), "=r"(r2), "=r"(r3) : "r"(addr));
}

#define BKT 32     // k-depth per tile (elements) = 16 kpair words
#define PA  20     // A smem row stride (words); conflict-free LDSM
#define PBK 20     // B smem row stride (words)
#define NBUF 3
#define AS_WORDS (NBUF*128*PA)              // 7680
#define BS_WORDS (NBUF*128*PBK)             // 7680
#define SMEM_BYTES ((AS_WORDS+BS_WORDS)*4)  // 61440

// MODE: 0 = fp32 out; 1 = fp16 out; 2 = fp16 out into head-A tail (coalesced rows)
template<int GELU, int MODE>
__global__ __launch_bounds__(256, 2)
void hgemm_kernel(const fp16* __restrict__ A_,
                  const uint32_t* __restrict__ Bp,
                  const float* __restrict__ bias, const float* __restrict__ bias2,
                  float* __restrict__ Cf, fp16* __restrict__ Ch,
                  int M, int Kd, int Nd) {
    extern __shared__ uint32_t smw[];
    uint32_t* Asw = smw;              // [NBUF][128][PA]
    uint32_t* Bsw = smw + AS_WORDS;   // [NBUF][128 n][PBK]

    const int tid  = threadIdx.x;
    const int lane = tid & 31, wid = tid >> 5;
    const int gid  = lane >> 2, tig = lane & 3;
    const int wm   = (wid & 1) * 64;
    const int wn   = (wid >> 1) * 32;
    const int m0   = blockIdx.y * 128;
    const int n0   = blockIdx.x * 128;
    const bool wactive = (n0 + wn) < Nd;

    const uint32_t As_base = (uint32_t)__cvta_generic_to_shared(Asw);
    const uint32_t Bs_base = (uint32_t)__cvta_generic_to_shared(Bsw);

    const int a_rowl = wm + (lane & 15);
    const int a_koff = (lane >> 4) * 4;
    const int b_rowl = wn + (lane & 7) + ((lane >> 4) << 3);
    const int b_koff = ((lane >> 3) & 1) * 4;

    float4 acc[4][4];
    #pragma unroll
    for (int i = 0; i < 4; ++i)
        #pragma unroll
        for (int j = 0; j < 4; ++j) acc[i][j] = make_float4(0.f, 0.f, 0.f, 0.f);

    auto fill = [&](int t, int buf) {
        const int k0 = t * BKT;
        // A: 128 rows x 4 chunks(16B = 8 fp16)
        #pragma unroll
        for (int i = 0; i < 2; ++i) {
            int c = tid + 256 * i;
            int rr = (c >> 2) & 127, ch = c & 3;
            const fp16* src = A_ + (size_t)(m0 + rr) * Kd + k0 + ch * 8;
            uint32_t dst = As_base + (uint32_t)((((buf*128 + rr) * PA) + ch * 4) * 4);
            cp16(dst, src, 16);
        }
        // B (n-major): 128 n-rows x 4 chunks of 4 kpair-words
        #pragma unroll
        for (int i = 0; i < 2; ++i) {
            int c = tid + 256 * i;
            int rr = (c >> 2) & 127, ch = c & 3;
            int n = n0 + rr;
            const uint32_t* src = Bp;
            int bytes = 0;
            if (n < Nd) { src = Bp + (size_t)n * (Kd/2) + k0/2 + ch * 4; bytes = 16; }
            uint32_t dst = Bs_base + (uint32_t)((((buf*128 + rr) * PBK) + ch * 4) * 4);
            cp16(dst, src, bytes);
        }
    };

    const int nk = Kd / BKT;
    // prologue: 2 chunks in flight
    fill(0, 0);
    asm volatile("cp.async.commit_group;");
    if (nk > 1) {
        fill(1, 1);
        asm volatile("cp.async.commit_group;");
        asm volatile("cp.async.wait_group 1;");
    } else {
        asm volatile("cp.async.wait_group 0;");
    }
    __syncthreads();

    for (int t = 0; t < nk; ++t) {
        const int buf = t % NBUF;
        if (t + 2 < nk) {
            fill(t + 2, (t + 2) % NBUF);
            asm volatile("cp.async.commit_group;");
        }
        if (wactive) {
            #pragma unroll
            for (int kk2 = 0; kk2 < 16; kk2 += 8) {
                const uint32_t aoff = As_base +
                    (uint32_t)((((buf*128 + a_rowl) * PA) + kk2 + a_koff) * 4);
                const uint32_t boff = Bs_base +
                    (uint32_t)((((buf*128 + b_rowl) * PBK) + kk2 + b_koff) * 4);

                uint32_t bh[4][2], af[4][4];
                ldsm4(bh[0][0], bh[0][1], bh[1][0], bh[1][1], boff);
                ldsm4(bh[2][0], bh[2][1], bh[3][0], bh[3][1], boff + 16*PBK*4);
                #pragma unroll
                for (int mt = 0; mt < 4; ++mt)
                    ldsm4(af[mt][0], af[mt][1], af[mt][2], af[mt][3],
                          aoff + mt * 16*PA*4);
                #pragma unroll
                for (int mt = 0; mt < 4; ++mt)
                    #pragma unroll
                    for (int nt = 0; nt < 4; ++nt)
                        mma16(acc[mt][nt], af[mt][0], af[mt][1], af[mt][2], af[mt][3],
                              bh[nt][0], bh[nt][1]);
            }
        }
        if (t + 1 < nk) {
            if (t + 2 < nk) asm volatile("cp.async.wait_group 1;");
            else            asm volatile("cp.async.wait_group 0;");
            __syncthreads();
        }
    }

    // epilogue (paired stores; col even, Nd even)
    auto emit2 = [&](int row, int col, float v0, float v1) {
        if (col >= Nd) return;
        v0 += bias[col]; v1 += bias[col + 1];
        if (bias2) { v0 += bias2[col]; v1 += bias2[col + 1]; }
        if (GELU) {
            v0 = 0.5f * v0 * (1.0f + erff(v0 * 0.70710678118654752f));
            v1 = 0.5f * v1 * (1.0f + erff(v1 * 0.70710678118654752f));
        }
        if (MODE == 0) {
            *reinterpret_cast<float2*>(&Cf[(size_t)row * Nd + col]) = make_float2(v0, v1);
        } else if (MODE == 1) {
            *reinterpret_cast<uint32_t*>(&Ch[(size_t)row * Nd + col]) =
                hpack(__float2half_rn(v0), __float2half_rn(v1));
        } else {
            // head-A tail, coalesced: row bc*4+s -> g_A[bc*1024 + 512 + s*128 + col]
            size_t i0 = ((size_t)(row >> 2)) * 1024 + 512 + (size_t)(row & 3) * 128 + col;
            *reinterpret_cast<uint32_t*>(&Ch[i0]) =
                hpack(__float2half_rn(v0), __float2half_rn(v1));
        }
    };
    #pragma unroll
    for (int mt = 0; mt < 4; ++mt) {
        int r0 = m0 + wm + mt * 16 + gid;
        #pragma unroll
        for (int nt = 0; nt < 4; ++nt) {
            int c0 = n0 + wn + nt * 8 + 2 * tig;
            float4 c = acc[mt][nt];
            emit2(r0,     c0, c.x, c.y);
            emit2(r0 + 8, c0, c.z, c.w);
        }
    }
}

// ---------------- final: denorm + transpose to [B, PRED, C] ----------------
__global__ void final_kernel(const float* __restrict__ rw,
                             const float* __restrict__ rb,
                             float* __restrict__ out) {
    __shared__ float sm[32][33];
    int b  = blockIdx.z;
    int p0 = blockIdx.x * 32, c0 = blockIdx.y * 32;
    int tx = threadIdx.x, ty = threadIdx.y;
    int p = p0 + tx, c = c0 + ty;
    if (p < PREDL && c < CH)
        sm[ty][tx] = g_y[((size_t)(b*CH + c)) * PREDL + p];
    __syncthreads();
    int cw = c0 + tx, pw = p0 + ty;
    if (cw < CH && pw < PREDL) {
        float v = sm[tx][ty];
        v = (v - rb[cw]) / (rw[cw] + 1e-10f);
        v = v * g_std[b*CH + cw] + g_mean[b*CH + cw];
        out[((size_t)b * PREDL + pw) * CH + cw] = v;
    }
}

// ---------------- launch ----------------
extern "C" void kernel_launch(void* const* d_in, const int* in_sizes, int n_in,
                              void* d_out, int out_size) {
    const float* x   = (const float*)d_in[0];
    const float* rw  = (const float*)d_in[1];
    const float* rb  = (const float*)d_in[2];
    const float* W11 = (const float*)d_in[3];
    const float* b11 = (const float*)d_in[4];
    const float* W12 = (const float*)d_in[5];
    const float* b12 = (const float*)d_in[6];
    const float* W21 = (const float*)d_in[7];
    const float* b21 = (const float*)d_in[8];
    const float* W22 = (const float*)d_in[9];
    const float* b22 = (const float*)d_in[10];
    const float* Wtr = (const float*)d_in[11];
    const float* btr = (const float*)d_in[12];
    const float* Wse = (const float*)d_in[13];
    const float* bse = (const float*)d_in[14];
    float* out = (float*)d_out;
    (void)in_sizes; (void)n_in; (void)out_size;

    fp16 *p_A, *p_xs, *p_h;
    uint32_t *p_w11p, *p_w12p, *p_w21p, *p_w22p, *p_w2p;
    float *p_y;
    cudaGetSymbolAddress((void**)&p_A,  g_A);
    cudaGetSymbolAddress((void**)&p_xs, g_xs);
    cudaGetSymbolAddress((void**)&p_h,  g_h);
    cudaGetSymbolAddress((void**)&p_w11p, g_w11p);
    cudaGetSymbolAddress((void**)&p_w12p, g_w12p);
    cudaGetSymbolAddress((void**)&p_w21p, g_w21p);
    cudaGetSymbolAddress((void**)&p_w22p, g_w22p);
    cudaGetSymbolAddress((void**)&p_w2p,  g_w2p);
    cudaGetSymbolAddress((void**)&p_y,    g_y);

    cudaFuncSetAttribute(hgemm_kernel<1,1>, cudaFuncAttributeMaxDynamicSharedMemorySize, SMEM_BYTES);
    cudaFuncSetAttribute(hgemm_kernel<0,1>, cudaFuncAttributeMaxDynamicSharedMemorySize, SMEM_BYTES);
    cudaFuncSetAttribute(hgemm_kernel<0,2>, cudaFuncAttributeMaxDynamicSharedMemorySize, SMEM_BYTES);
    cudaFuncSetAttribute(hgemm_kernel<0,0>, cudaFuncAttributeMaxDynamicSharedMemorySize, SMEM_BYTES);

    // 1) fused weight packing (one launch)
    pack_all_kernel<<<(SEG5 + 255)/256, 256>>>(W11, W12, W21, W22, Wtr, Wse);
    // 2) fused stats + normalize + decomposition (+ fp16, interleave)
    norm_decomp_kernel<<<dim3((CH + NDC - 1) / NDC, BATCH), 256>>>(x, rw, rb);
    // 3) seasonal MLP (fp16 tensor-core GEMMs)
    hgemm_kernel<1,1><<<dim3(HID / 128, MMLP / 128), 256, SMEM_BYTES>>>(
        p_xs, p_w11p, b11, nullptr, nullptr, p_h, MMLP, NSEG, HID);
    hgemm_kernel<0,1><<<dim3(1,         MMLP / 128), 256, SMEM_BYTES>>>(
        p_h, p_w12p, b12, nullptr, nullptr, p_xs, MMLP, HID, NSEG);
    hgemm_kernel<1,1><<<dim3(HID / 128, MMLP / 128), 256, SMEM_BYTES>>>(
        p_xs, p_w21p, b21, nullptr, nullptr, p_h, MMLP, NSEG, HID);
    hgemm_kernel<0,2><<<dim3(1,         MMLP / 128), 256, SMEM_BYTES>>>(
        p_h, p_w22p, b22, nullptr, nullptr, p_A, MMLP, HID, NSEG);
    // 4) fused heads: [trend|sea(perm)] @ [W_tr;W_se(perm)] (fp32 out)
    hgemm_kernel<0,0><<<dim3((PREDL + 127) / 128, BC / 128), 256, SMEM_BYTES>>>(
        p_A, p_w2p, btr, bse, p_y, nullptr, BC, 1024, PREDL);
    // 5) denorm + transpose
    final_kernel<<<dim3((PREDL + 31) / 32, (CH + 31) / 32, BATCH), dim3(32, 32)>>>(rw, rb, out);
}